// round 7
// baseline (speedup 1.0000x reference)
#include <cuda_runtime.h>
#include <math.h>

// Problem constants
#define B_ 2
#define S_ 2048
#define D_ 1024
#define H_ 16
#define DK_ 64

// ---------------- scratch (no cudaMalloc allowed) ----------------
__device__ float g_q[(size_t)B_ * S_ * D_];
__device__ float g_k[(size_t)B_ * S_ * D_];
__device__ float g_v[(size_t)B_ * S_ * D_];
__device__ float g_ctx[(size_t)B_ * S_ * D_];
// per-row exp partial sums: [z][row][16 bn-tiles * 4 wn] = 64 partials/row
__device__ float g_partial[(size_t)B_ * H_ * S_ * 64];

// ---------------- TF32 helpers ----------------
__device__ __forceinline__ unsigned f2tf32(float x) {
    unsigned r;
    asm("cvt.rna.tf32.f32 %0, %1;" : "=r"(r) : "f"(x));
    return r;
}

__device__ __forceinline__ void mma_tf32(float c[4],
    unsigned a0, unsigned a1, unsigned a2, unsigned a3,
    unsigned b0, unsigned b1)
{
    asm volatile(
        "mma.sync.aligned.m16n8k8.row.col.f32.tf32.tf32.f32 "
        "{%0,%1,%2,%3}, {%4,%5,%6,%7}, {%8,%9}, {%0,%1,%2,%3};"
        : "+f"(c[0]), "+f"(c[1]), "+f"(c[2]), "+f"(c[3])
        : "r"(a0), "r"(a1), "r"(a2), "r"(a3), "r"(b0), "r"(b1));
}

__device__ __forceinline__ void sts4(unsigned (*s)[136], int k, int r, float4 v) {
    s[k + 0][r] = f2tf32(v.x);
    s[k + 1][r] = f2tf32(v.y);
    s[k + 2][r] = f2tf32(v.z);
    s[k + 3][r] = f2tf32(v.w);
}

// ================= generic TF32 NT GEMM =================
// C[M,N] = scale * A[M,K] @ B[N,K]^T (+ bias[N]), or exp-epilogue for QK.
// Block 128x128, 256 threads (8 warps as 2x4 grid of 64x32 warp tiles), BK=16.
template<int KDIM, bool HAS_BIAS, bool EXP_MODE>
__global__ __launch_bounds__(256, 2) void gemm_tf32(
    const float* __restrict__ A, const float* __restrict__ Bm,
    const float* __restrict__ bias, float* __restrict__ C,
    int lda, int ldb, int ldc,
    size_t aB, size_t aH, size_t bB, size_t bH, size_t cB, size_t cH,
    float scale, float* __restrict__ partial)
{
    __shared__ unsigned As[2][16][136];
    __shared__ unsigned Bs[2][16][136];

    const int tid  = threadIdx.x;
    const int lane = tid & 31;
    const int wid  = tid >> 5;
    const int wm   = wid & 1;            // 0..1 -> 64-row half
    const int wn   = wid >> 1;           // 0..3 -> 32-col quarter
    const int bm   = blockIdx.y * 128;
    const int bn   = blockIdx.x * 128;
    const int z    = blockIdx.z;
    const int zb   = z >> 4, zh = z & 15;

    // conflict-free loader mapping: row = tid & 127, k-half = (tid>>7)*8
    const int arow = tid & 127;
    const int ak   = (tid >> 7) * 8;
    const float* Ap = A + zb * aB + zh * aH + (size_t)(bm + arow) * lda + ak;
    const float* Bp = Bm + zb * bB + zh * bH + (size_t)(bn + arow) * ldb + ak;

    float acc[4][4][4];
#pragma unroll
    for (int i = 0; i < 4; i++)
#pragma unroll
        for (int j = 0; j < 4; j++)
#pragma unroll
            for (int e = 0; e < 4; e++) acc[i][j][e] = 0.f;

    float4 a0, a1, b0, b1;
    a0 = *(const float4*)(Ap);
    a1 = *(const float4*)(Ap + 4);
    b0 = *(const float4*)(Bp);
    b1 = *(const float4*)(Bp + 4);
    sts4(As[0], ak, arow, a0);
    sts4(As[0], ak + 4, arow, a1);
    sts4(Bs[0], ak, arow, b0);
    sts4(Bs[0], ak + 4, arow, b1);
    __syncthreads();

    const int NIT = KDIM / 16;
    const int mg  = wm * 64 + (lane >> 2);
    const int ng  = wn * 32 + (lane >> 2);
    const int kl  = lane & 3;

    for (int it = 0; it < NIT; it++) {
        const int cur = it & 1;
        if (it + 1 < NIT) {
            const int k0 = (it + 1) * 16;
            a0 = *(const float4*)(Ap + k0);
            a1 = *(const float4*)(Ap + k0 + 4);
            b0 = *(const float4*)(Bp + k0);
            b1 = *(const float4*)(Bp + k0 + 4);
        }
#pragma unroll
        for (int s = 0; s < 2; s++) {
            const int kb = s * 8 + kl;
            unsigned af[4][4];
#pragma unroll
            for (int i = 0; i < 4; i++) {
                af[i][0] = As[cur][kb    ][mg + i * 16];
                af[i][1] = As[cur][kb    ][mg + i * 16 + 8];
                af[i][2] = As[cur][kb + 4][mg + i * 16];
                af[i][3] = As[cur][kb + 4][mg + i * 16 + 8];
            }
            unsigned bf[4][2];
#pragma unroll
            for (int j = 0; j < 4; j++) {
                bf[j][0] = Bs[cur][kb    ][ng + j * 8];
                bf[j][1] = Bs[cur][kb + 4][ng + j * 8];
            }
#pragma unroll
            for (int j = 0; j < 4; j++)
#pragma unroll
                for (int i = 0; i < 4; i++)
                    mma_tf32(acc[i][j], af[i][0], af[i][1], af[i][2], af[i][3],
                             bf[j][0], bf[j][1]);
        }
        if (it + 1 < NIT) {
            const int nxt = cur ^ 1;
            sts4(As[nxt], ak, arow, a0);
            sts4(As[nxt], ak + 4, arow, a1);
            sts4(Bs[nxt], ak, arow, b0);
            sts4(Bs[nxt], ak + 4, arow, b1);
            __syncthreads();
        }
    }

    // epilogue
    float* Cp = C + zb * cB + zh * cH;
    const int rl   = wm * 64 + (lane >> 2);      // local row within 128-tile
    const int col0 = bn + wn * 32 + (lane & 3) * 2;

    if (EXP_MODE) {
        // write exp(scale*s); accumulate per-row partial sums over this warp's 32 cols
#pragma unroll
        for (int i = 0; i < 4; i++) {
            const int rlo = bm + rl + i * 16;
            const int rhi = rlo + 8;
            float pl = 0.f, ph = 0.f;
#pragma unroll
            for (int j = 0; j < 4; j++) {
                float e0 = __expf(acc[i][j][0] * scale);
                float e1 = __expf(acc[i][j][1] * scale);
                float e2 = __expf(acc[i][j][2] * scale);
                float e3 = __expf(acc[i][j][3] * scale);
                float2 lo; lo.x = e0; lo.y = e1;
                float2 hi; hi.x = e2; hi.y = e3;
                *(float2*)&Cp[(size_t)rlo * ldc + col0 + j * 8] = lo;
                *(float2*)&Cp[(size_t)rhi * ldc + col0 + j * 8] = hi;
                pl += e0 + e1;
                ph += e2 + e3;
            }
            // reduce across the 4 lanes of the quad (lane&3 = 0..3)
            pl += __shfl_xor_sync(0xffffffffu, pl, 1);
            pl += __shfl_xor_sync(0xffffffffu, pl, 2);
            ph += __shfl_xor_sync(0xffffffffu, ph, 1);
            ph += __shfl_xor_sync(0xffffffffu, ph, 2);
            if ((lane & 3) == 0) {
                partial[((size_t)z * S_ + rlo) * 64 + blockIdx.x * 4 + wn] = pl;
                partial[((size_t)z * S_ + rhi) * 64 + blockIdx.x * 4 + wn] = ph;
            }
        }
    } else {
        float2 bvj[4];
        if (HAS_BIAS) {
#pragma unroll
            for (int j = 0; j < 4; j++)
                bvj[j] = *(const float2*)&bias[col0 + j * 8];
        }
#pragma unroll
        for (int i = 0; i < 4; i++) {
#pragma unroll
            for (int j = 0; j < 4; j++) {
                const int r = bm + rl + i * 16;
                const int c = col0 + j * 8;
                float2 lo, hi;
                lo.x = acc[i][j][0] * scale;
                lo.y = acc[i][j][1] * scale;
                hi.x = acc[i][j][2] * scale;
                hi.y = acc[i][j][3] * scale;
                if (HAS_BIAS) {
                    lo.x += bvj[j].x; lo.y += bvj[j].y;
                    hi.x += bvj[j].x; hi.y += bvj[j].y;
                }
                *(float2*)&Cp[(size_t)r * ldc + c]       = lo;
                *(float2*)&Cp[(size_t)(r + 8) * ldc + c] = hi;
            }
        }
    }
}

// ================= PV: normalize attn in place + ctx = P @ V =================
// Block 128(M)x64(N), 256 threads (8 warps as 4x2 grid of 32x32 warp tiles), BK=32.
// Prologue: reduce 64 exp-partials per row -> 1/rowsum.
// Main loop streams exp-scores, multiplies by inv (final attn value), writes it
// back in place, and feeds it to tf32 MMA against V.
#define PV_PS_WORDS (2 * 32 * 136)
#define PV_VS_WORDS (2 * 32 * 72)
#define PV_SMEM_BYTES ((PV_PS_WORDS + PV_VS_WORDS + 128) * 4)
#define PSH(b,k,r) smP[((b) * 32 + (k)) * 136 + (r)]
#define VSH(b,k,r) smV[((b) * 32 + (k)) * 72 + (r)]

__global__ __launch_bounds__(256, 2) void pv_tf32(
    float* __restrict__ attn, const float* __restrict__ Vg,
    float* __restrict__ ctx, const float* __restrict__ partial)
{
    extern __shared__ unsigned smraw[];
    unsigned* smP = smraw;
    unsigned* smV = smraw + PV_PS_WORDS;
    float* s_inv  = (float*)(smraw + PV_PS_WORDS + PV_VS_WORDS);

    const int tid  = threadIdx.x;
    const int lane = tid & 31;
    const int wid  = tid >> 5;
    const int wm   = wid & 3;         // 32-row quarter
    const int wn   = wid >> 2;        // 32-col half
    const int bm   = blockIdx.x * 128;
    const int z    = blockIdx.y;
    const int zb   = z >> 4, zh = z & 15;

    // ---- prologue: per-row inverse sums (64 partials per row) ----
    {
        const int r = tid >> 1;
        const float* pp = partial + ((size_t)z * S_ + bm + r) * 64 + (tid & 1) * 32;
        float s = 0.f;
#pragma unroll
        for (int f = 0; f < 8; f++) {
            float4 u = ((const float4*)pp)[f];
            s += (u.x + u.y) + (u.z + u.w);
        }
        s += __shfl_xor_sync(0xffffffffu, s, 1);
        if (!(tid & 1)) s_inv[r] = 1.f / s;
    }
    __syncthreads();

    // P loader: row = tid & 127, k-half = (tid>>7)*16 (BK=32, 16 elems/thread)
    const int prow = tid & 127;
    const int pk   = (tid >> 7) * 16;
    float* P = attn + (size_t)z * S_ * S_ + (size_t)(bm + prow) * S_ + pk;
    const float inv = s_inv[prow];

    // V loader: 32x64 tile, 8 elems/thread
    const int vr = tid >> 3;              // 0..31 (k within tile)
    const int vc = (tid & 7) * 8;         // 0..56
    const float* Vp = Vg + (size_t)zb * S_ * D_ + (size_t)zh * DK_
                      + (size_t)vr * D_ + vc;

    float acc[2][4][4];
#pragma unroll
    for (int i = 0; i < 2; i++)
#pragma unroll
        for (int j = 0; j < 4; j++)
#pragma unroll
            for (int e = 0; e < 4; e++) acc[i][j][e] = 0.f;

    float4 p0, p1, p2, p3, v0, v1;
    // tile 0
    p0 = *(const float4*)(P);
    p1 = *(const float4*)(P + 4);
    p2 = *(const float4*)(P + 8);
    p3 = *(const float4*)(P + 12);
    p0.x *= inv; p0.y *= inv; p0.z *= inv; p0.w *= inv;
    p1.x *= inv; p1.y *= inv; p1.z *= inv; p1.w *= inv;
    p2.x *= inv; p2.y *= inv; p2.z *= inv; p2.w *= inv;
    p3.x *= inv; p3.y *= inv; p3.z *= inv; p3.w *= inv;
    *(float4*)(P)      = p0;    // final normalized attn
    *(float4*)(P + 4)  = p1;
    *(float4*)(P + 8)  = p2;
    *(float4*)(P + 12) = p3;
    v0 = *(const float4*)(Vp);
    v1 = *(const float4*)(Vp + 4);
    {
        PSH(0, pk + 0,  prow) = f2tf32(p0.x); PSH(0, pk + 1,  prow) = f2tf32(p0.y);
        PSH(0, pk + 2,  prow) = f2tf32(p0.z); PSH(0, pk + 3,  prow) = f2tf32(p0.w);
        PSH(0, pk + 4,  prow) = f2tf32(p1.x); PSH(0, pk + 5,  prow) = f2tf32(p1.y);
        PSH(0, pk + 6,  prow) = f2tf32(p1.z); PSH(0, pk + 7,  prow) = f2tf32(p1.w);
        PSH(0, pk + 8,  prow) = f2tf32(p2.x); PSH(0, pk + 9,  prow) = f2tf32(p2.y);
        PSH(0, pk + 10, prow) = f2tf32(p2.z); PSH(0, pk + 11, prow) = f2tf32(p2.w);
        PSH(0, pk + 12, prow) = f2tf32(p3.x); PSH(0, pk + 13, prow) = f2tf32(p3.y);
        PSH(0, pk + 14, prow) = f2tf32(p3.z); PSH(0, pk + 15, prow) = f2tf32(p3.w);
        VSH(0, vr, vc + 0) = f2tf32(v0.x); VSH(0, vr, vc + 1) = f2tf32(v0.y);
        VSH(0, vr, vc + 2) = f2tf32(v0.z); VSH(0, vr, vc + 3) = f2tf32(v0.w);
        VSH(0, vr, vc + 4) = f2tf32(v1.x); VSH(0, vr, vc + 5) = f2tf32(v1.y);
        VSH(0, vr, vc + 6) = f2tf32(v1.z); VSH(0, vr, vc + 7) = f2tf32(v1.w);
    }
    __syncthreads();

    const int NIT = S_ / 32;   // 64
    const int mg  = wm * 32 + (lane >> 2);
    const int ng  = wn * 32 + (lane >> 2);
    const int kl  = lane & 3;

    for (int it = 0; it < NIT; it++) {
        const int cur = it & 1;
        if (it + 1 < NIT) {
            const int k0 = (it + 1) * 32;
            p0 = *(const float4*)(P + k0);
            p1 = *(const float4*)(P + k0 + 4);
            p2 = *(const float4*)(P + k0 + 8);
            p3 = *(const float4*)(P + k0 + 12);
            p0.x *= inv; p0.y *= inv; p0.z *= inv; p0.w *= inv;
            p1.x *= inv; p1.y *= inv; p1.z *= inv; p1.w *= inv;
            p2.x *= inv; p2.y *= inv; p2.z *= inv; p2.w *= inv;
            p3.x *= inv; p3.y *= inv; p3.z *= inv; p3.w *= inv;
            *(float4*)(P + k0)      = p0;
            *(float4*)(P + k0 + 4)  = p1;
            *(float4*)(P + k0 + 8)  = p2;
            *(float4*)(P + k0 + 12) = p3;
            v0 = *(const float4*)(Vp + (size_t)k0 * D_);
            v1 = *(const float4*)(Vp + (size_t)k0 * D_ + 4);
        }
#pragma unroll
        for (int s = 0; s < 4; s++) {
            const int kb = s * 8 + kl;
            unsigned af[2][4];
#pragma unroll
            for (int i = 0; i < 2; i++) {
                af[i][0] = PSH(cur, kb,     mg + i * 16);
                af[i][1] = PSH(cur, kb,     mg + i * 16 + 8);
                af[i][2] = PSH(cur, kb + 4, mg + i * 16);
                af[i][3] = PSH(cur, kb + 4, mg + i * 16 + 8);
            }
            unsigned bf[4][2];
#pragma unroll
            for (int j = 0; j < 4; j++) {
                bf[j][0] = VSH(cur, kb,     ng + j * 8);
                bf[j][1] = VSH(cur, kb + 4, ng + j * 8);
            }
#pragma unroll
            for (int j = 0; j < 4; j++)
#pragma unroll
                for (int i = 0; i < 2; i++)
                    mma_tf32(acc[i][j], af[i][0], af[i][1], af[i][2], af[i][3],
                             bf[j][0], bf[j][1]);
        }
        if (it + 1 < NIT) {
            const int nxt = cur ^ 1;
            PSH(nxt, pk + 0,  prow) = f2tf32(p0.x); PSH(nxt, pk + 1,  prow) = f2tf32(p0.y);
            PSH(nxt, pk + 2,  prow) = f2tf32(p0.z); PSH(nxt, pk + 3,  prow) = f2tf32(p0.w);
            PSH(nxt, pk + 4,  prow) = f2tf32(p1.x); PSH(nxt, pk + 5,  prow) = f2tf32(p1.y);
            PSH(nxt, pk + 6,  prow) = f2tf32(p1.z); PSH(nxt, pk + 7,  prow) = f2tf32(p1.w);
            PSH(nxt, pk + 8,  prow) = f2tf32(p2.x); PSH(nxt, pk + 9,  prow) = f2tf32(p2.y);
            PSH(nxt, pk + 10, prow) = f2tf32(p2.z); PSH(nxt, pk + 11, prow) = f2tf32(p2.w);
            PSH(nxt, pk + 12, prow) = f2tf32(p3.x); PSH(nxt, pk + 13, prow) = f2tf32(p3.y);
            PSH(nxt, pk + 14, prow) = f2tf32(p3.z); PSH(nxt, pk + 15, prow) = f2tf32(p3.w);
            VSH(nxt, vr, vc + 0) = f2tf32(v0.x); VSH(nxt, vr, vc + 1) = f2tf32(v0.y);
            VSH(nxt, vr, vc + 2) = f2tf32(v0.z); VSH(nxt, vr, vc + 3) = f2tf32(v0.w);
            VSH(nxt, vr, vc + 4) = f2tf32(v1.x); VSH(nxt, vr, vc + 5) = f2tf32(v1.y);
            VSH(nxt, vr, vc + 6) = f2tf32(v1.z); VSH(nxt, vr, vc + 7) = f2tf32(v1.w);
            __syncthreads();
        }
    }

    float* Cc = ctx + (size_t)zb * S_ * D_ + (size_t)zh * DK_;
    const int row0 = bm + wm * 32 + (lane >> 2);
    const int col0 = wn * 32 + (lane & 3) * 2;
#pragma unroll
    for (int i = 0; i < 2; i++) {
#pragma unroll
        for (int j = 0; j < 4; j++) {
            const int r = row0 + i * 16;
            const int c = col0 + j * 8;
            float2 lo, hi;
            lo.x = acc[i][j][0]; lo.y = acc[i][j][1];
            hi.x = acc[i][j][2]; hi.y = acc[i][j][3];
            *(float2*)&Cc[(size_t)r * D_ + c]       = lo;
            *(float2*)&Cc[(size_t)(r + 8) * D_ + c] = hi;
        }
    }
}

// ---------------- launch ----------------
extern "C" void kernel_launch(void* const* d_in, const int* in_sizes, int n_in,
                              void* d_out, int out_size)
{
    const float* query = (const float*)d_in[0];
    const float* key   = (const float*)d_in[1];
    const float* value = (const float*)d_in[2];
    const float* Wq    = (const float*)d_in[3];
    const float* bq    = (const float*)d_in[4];
    const float* Wk    = (const float*)d_in[5];
    const float* bk    = (const float*)d_in[6];
    const float* Wv    = (const float*)d_in[7];
    const float* bv    = (const float*)d_in[8];
    const float* Wo    = (const float*)d_in[9];
    const float* bo    = (const float*)d_in[10];

    float* out  = (float*)d_out;                          // (B,S,D)
    float* attn = out + (size_t)B_ * S_ * D_;             // (B,H,S,S)

    float *q, *k, *v, *ctx, *part;
    cudaGetSymbolAddress((void**)&q,    g_q);
    cudaGetSymbolAddress((void**)&k,    g_k);
    cudaGetSymbolAddress((void**)&v,    g_v);
    cudaGetSymbolAddress((void**)&ctx,  g_ctx);
    cudaGetSymbolAddress((void**)&part, g_partial);

    cudaFuncSetAttribute(pv_tf32, cudaFuncAttributeMaxDynamicSharedMemorySize,
                         PV_SMEM_BYTES);

    // Projections: C[4096,1024] = X @ W^T + b
    dim3 pgrid(D_ / 128, (B_ * S_) / 128, 1);
    gemm_tf32<D_, true, false><<<pgrid, 256>>>(query, Wq, bq, q,
        D_, D_, D_, 0, 0, 0, 0, 0, 0, 1.f, nullptr);
    gemm_tf32<D_, true, false><<<pgrid, 256>>>(key, Wk, bk, k,
        D_, D_, D_, 0, 0, 0, 0, 0, 0, 1.f, nullptr);
    gemm_tf32<D_, true, false><<<pgrid, 256>>>(value, Wv, bv, v,
        D_, D_, D_, 0, 0, 0, 0, 0, 0, 1.f, nullptr);

    // QK^T -> exp(scores) + row partial sums
    dim3 qkgrid(S_ / 128, S_ / 128, B_ * H_);
    gemm_tf32<DK_, false, true><<<qkgrid, 256>>>(q, k, nullptr, attn,
        D_, D_, S_,
        (size_t)S_ * D_, DK_,
        (size_t)S_ * D_, DK_,
        (size_t)H_ * S_ * S_, (size_t)S_ * S_,
        0.125f, part);

    // normalize attn in place + ctx = P @ V
    dim3 pvgrid(S_ / 128, B_ * H_);
    pv_tf32<<<pvgrid, 256, PV_SMEM_BYTES>>>(attn, v, ctx, part);

    // output projection
    gemm_tf32<D_, true, false><<<pgrid, 256>>>(ctx, Wo, bo, out,
        D_, D_, D_, 0, 0, 0, 0, 0, 0, 1.f, nullptr);
}

// round 8
// speedup vs baseline: 1.6301x; 1.6301x over previous
#include <cuda_runtime.h>
#include <cuda_fp16.h>
#include <math.h>
#include <stdint.h>

// Problem constants
#define B_ 2
#define S_ 2048
#define D_ 1024
#define H_ 16
#define DK_ 64

// ---------------- scratch (no cudaMalloc allowed) ----------------
__device__ float g_q[(size_t)B_ * S_ * D_];
__device__ float g_k[(size_t)B_ * S_ * D_];
__device__ float g_v[(size_t)B_ * S_ * D_];
__device__ float g_ctx[(size_t)B_ * S_ * D_];
// per-row exp partial sums: [z][row][16 bn-tiles * 4 wn] = 64 partials/row
__device__ float g_partial[(size_t)B_ * H_ * S_ * 64];

// ---------------- FP16 helpers ----------------
__device__ __forceinline__ uint32_t f2h2(float lo, float hi) {
    __half2 h = __floats2half2_rn(lo, hi);
    return *(uint32_t*)&h;
}

__device__ __forceinline__ void mma_f16(float c[4],
    uint32_t a0, uint32_t a1, uint32_t a2, uint32_t a3,
    uint32_t b0, uint32_t b1)
{
    asm volatile(
        "mma.sync.aligned.m16n8k16.row.col.f32.f16.f16.f32 "
        "{%0,%1,%2,%3}, {%4,%5,%6,%7}, {%8,%9}, {%0,%1,%2,%3};"
        : "+f"(c[0]), "+f"(c[1]), "+f"(c[2]), "+f"(c[3])
        : "r"(a0), "r"(a1), "r"(a2), "r"(a3), "r"(b0), "r"(b1));
}

// smem tiles: [8 k-pairs][136] uint32 (each = 2 consecutive-k fp16)
// sts4h: store 8 consecutive-k floats (two float4) for row r starting at pair kkb
#define STS8H(s, kkb, r, v0, v1) do { \
    (s)[(kkb) + 0][r] = f2h2((v0).x, (v0).y); \
    (s)[(kkb) + 1][r] = f2h2((v0).z, (v0).w); \
    (s)[(kkb) + 2][r] = f2h2((v1).x, (v1).y); \
    (s)[(kkb) + 3][r] = f2h2((v1).z, (v1).w); \
} while (0)

// ================= generic FP16 NT GEMM =================
// C[M,N] = scale * A[M,K] @ B[N,K]^T (+ bias[N]), or exp-epilogue for QK.
// Block 128x128, 256 threads (8 warps as 2x4 grid of 64x32 warp tiles), BK=16.
template<int KDIM, bool HAS_BIAS, bool EXP_MODE>
__global__ __launch_bounds__(256, 2) void gemm_f16(
    const float* __restrict__ A, const float* __restrict__ Bm,
    const float* __restrict__ bias, float* __restrict__ C,
    int lda, int ldb, int ldc,
    size_t aB, size_t aH, size_t bB, size_t bH, size_t cB, size_t cH,
    float scale, float* __restrict__ partial)
{
    __shared__ uint32_t As[2][8][136];
    __shared__ uint32_t Bs[2][8][136];

    const int tid  = threadIdx.x;
    const int lane = tid & 31;
    const int wid  = tid >> 5;
    const int wm   = wid & 1;            // 0..1 -> 64-row half
    const int wn   = wid >> 1;           // 0..3 -> 32-col quarter
    const int bm   = blockIdx.y * 128;
    const int bn   = blockIdx.x * 128;
    const int z    = blockIdx.z;
    const int zb   = z >> 4, zh = z & 15;

    // R4 loader mapping (LDG-optimal: 16 rows x 64B per warp)
    const int arow = tid >> 1;           // 0..127
    const int ak   = (tid & 1) * 8;      // k offset 0 or 8
    const int kkb  = (tid & 1) * 4;      // pair offset 0 or 4
    const float* Ap = A + zb * aB + zh * aH + (size_t)(bm + arow) * lda + ak;
    const float* Bp = Bm + zb * bB + zh * bH + (size_t)(bn + arow) * ldb + ak;

    float acc[4][4][4];
#pragma unroll
    for (int i = 0; i < 4; i++)
#pragma unroll
        for (int j = 0; j < 4; j++)
#pragma unroll
            for (int e = 0; e < 4; e++) acc[i][j][e] = 0.f;

    float4 a0, a1, b0, b1;
    a0 = *(const float4*)(Ap);
    a1 = *(const float4*)(Ap + 4);
    b0 = *(const float4*)(Bp);
    b1 = *(const float4*)(Bp + 4);
    STS8H(As[0], kkb, arow, a0, a1);
    STS8H(Bs[0], kkb, arow, b0, b1);
    __syncthreads();

    const int NIT = KDIM / 16;
    const int mg  = wm * 64 + (lane >> 2);
    const int ng  = wn * 32 + (lane >> 2);
    const int kl  = lane & 3;

    for (int it = 0; it < NIT; it++) {
        const int cur = it & 1;
        if (it + 1 < NIT) {
            const int k0 = (it + 1) * 16;
            a0 = *(const float4*)(Ap + k0);
            a1 = *(const float4*)(Ap + k0 + 4);
            b0 = *(const float4*)(Bp + k0);
            b1 = *(const float4*)(Bp + k0 + 4);
        }
        // one k16 slice
        {
            uint32_t af[4][4];
#pragma unroll
            for (int i = 0; i < 4; i++) {
                af[i][0] = As[cur][kl    ][mg + i * 16];
                af[i][1] = As[cur][kl    ][mg + i * 16 + 8];
                af[i][2] = As[cur][kl + 4][mg + i * 16];
                af[i][3] = As[cur][kl + 4][mg + i * 16 + 8];
            }
            uint32_t bf[4][2];
#pragma unroll
            for (int j = 0; j < 4; j++) {
                bf[j][0] = Bs[cur][kl    ][ng + j * 8];
                bf[j][1] = Bs[cur][kl + 4][ng + j * 8];
            }
#pragma unroll
            for (int j = 0; j < 4; j++)
#pragma unroll
                for (int i = 0; i < 4; i++)
                    mma_f16(acc[i][j], af[i][0], af[i][1], af[i][2], af[i][3],
                            bf[j][0], bf[j][1]);
        }
        if (it + 1 < NIT) {
            const int nxt = cur ^ 1;
            STS8H(As[nxt], kkb, arow, a0, a1);
            STS8H(Bs[nxt], kkb, arow, b0, b1);
            __syncthreads();
        }
    }

    // epilogue (identical to R4)
    float* Cp = C + zb * cB + zh * cH;
    const int rl   = wm * 64 + (lane >> 2);
    const int col0 = bn + wn * 32 + (lane & 3) * 2;

    if (EXP_MODE) {
#pragma unroll
        for (int i = 0; i < 4; i++) {
            const int rlo = bm + rl + i * 16;
            const int rhi = rlo + 8;
            float pl = 0.f, ph = 0.f;
#pragma unroll
            for (int j = 0; j < 4; j++) {
                float e0 = __expf(acc[i][j][0] * scale);
                float e1 = __expf(acc[i][j][1] * scale);
                float e2 = __expf(acc[i][j][2] * scale);
                float e3 = __expf(acc[i][j][3] * scale);
                float2 lo; lo.x = e0; lo.y = e1;
                float2 hi; hi.x = e2; hi.y = e3;
                *(float2*)&Cp[(size_t)rlo * ldc + col0 + j * 8] = lo;
                *(float2*)&Cp[(size_t)rhi * ldc + col0 + j * 8] = hi;
                pl += e0 + e1;
                ph += e2 + e3;
            }
            pl += __shfl_xor_sync(0xffffffffu, pl, 1);
            pl += __shfl_xor_sync(0xffffffffu, pl, 2);
            ph += __shfl_xor_sync(0xffffffffu, ph, 1);
            ph += __shfl_xor_sync(0xffffffffu, ph, 2);
            if ((lane & 3) == 0) {
                partial[((size_t)z * S_ + rlo) * 64 + blockIdx.x * 4 + wn] = pl;
                partial[((size_t)z * S_ + rhi) * 64 + blockIdx.x * 4 + wn] = ph;
            }
        }
    } else {
        float2 bvj[4];
        if (HAS_BIAS) {
#pragma unroll
            for (int j = 0; j < 4; j++)
                bvj[j] = *(const float2*)&bias[col0 + j * 8];
        }
#pragma unroll
        for (int i = 0; i < 4; i++) {
#pragma unroll
            for (int j = 0; j < 4; j++) {
                const int r = bm + rl + i * 16;
                const int c = col0 + j * 8;
                float2 lo, hi;
                lo.x = acc[i][j][0] * scale;
                lo.y = acc[i][j][1] * scale;
                hi.x = acc[i][j][2] * scale;
                hi.y = acc[i][j][3] * scale;
                if (HAS_BIAS) {
                    lo.x += bvj[j].x; lo.y += bvj[j].y;
                    hi.x += bvj[j].x; hi.y += bvj[j].y;
                }
                *(float2*)&Cp[(size_t)r * ldc + c]       = lo;
                *(float2*)&Cp[(size_t)(r + 8) * ldc + c] = hi;
            }
        }
    }
}

// ================= PV: normalize attn in place + ctx = P @ V =================
// Block 128(M)x64(N), 256 threads (8 warps as 4x2 grid of 32x32 warp tiles), BK=16.
__global__ __launch_bounds__(256, 2) void pv_f16(
    float* __restrict__ attn, const float* __restrict__ Vg,
    float* __restrict__ ctx, const float* __restrict__ partial)
{
    __shared__ uint32_t Ps[2][8][136];
    __shared__ uint32_t Vs[2][8][72];
    __shared__ float s_inv[128];

    const int tid  = threadIdx.x;
    const int lane = tid & 31;
    const int wid  = tid >> 5;
    const int wm   = wid & 3;         // 32-row quarter
    const int wn   = wid >> 2;        // 32-col half
    const int bm   = blockIdx.x * 128;
    const int z    = blockIdx.y;
    const int zb   = z >> 4, zh = z & 15;

    // ---- prologue: per-row inverse sums (64 partials per row) ----
    {
        const int r = tid >> 1;
        const float* pp = partial + ((size_t)z * S_ + bm + r) * 64 + (tid & 1) * 32;
        float s = 0.f;
#pragma unroll
        for (int f = 0; f < 8; f++) {
            float4 u = ((const float4*)pp)[f];
            s += (u.x + u.y) + (u.z + u.w);
        }
        s += __shfl_xor_sync(0xffffffffu, s, 1);
        if (!(tid & 1)) s_inv[r] = 1.f / s;
    }
    __syncthreads();

    // P loader (R4 mapping)
    const int prow = tid >> 1;
    const int pk   = (tid & 1) * 8;
    const int kkb  = (tid & 1) * 4;
    float* P = attn + (size_t)z * S_ * S_ + (size_t)(bm + prow) * S_ + pk;
    const float inv = s_inv[prow];

    // V loader: warp u loads V-tile rows 2u,2u+1; lane covers n = 2*lane..2*lane+1
    const int vu = wid;                 // pair index 0..7
    const int vn = lane * 2;            // n offset
    const float* Vbase = Vg + (size_t)zb * S_ * D_ + (size_t)zh * DK_ + vn;

    float acc[2][4][4];
#pragma unroll
    for (int i = 0; i < 2; i++)
#pragma unroll
        for (int j = 0; j < 4; j++)
#pragma unroll
            for (int e = 0; e < 4; e++) acc[i][j][e] = 0.f;

    float4 p0, p1;
    float2 ve, vo;
    // tile 0
    p0 = *(const float4*)(P);
    p1 = *(const float4*)(P + 4);
    p0.x *= inv; p0.y *= inv; p0.z *= inv; p0.w *= inv;
    p1.x *= inv; p1.y *= inv; p1.z *= inv; p1.w *= inv;
    *(float4*)(P)     = p0;    // final normalized attn
    *(float4*)(P + 4) = p1;
    ve = *(const float2*)(Vbase + (size_t)(2 * vu) * D_);
    vo = *(const float2*)(Vbase + (size_t)(2 * vu + 1) * D_);
    STS8H(Ps[0], kkb, prow, p0, p1);
    Vs[0][vu][vn]     = f2h2(ve.x, vo.x);
    Vs[0][vu][vn + 1] = f2h2(ve.y, vo.y);
    __syncthreads();

    const int NIT = S_ / 16;
    const int mg  = wm * 32 + (lane >> 2);
    const int ng  = wn * 32 + (lane >> 2);
    const int kl  = lane & 3;

    for (int it = 0; it < NIT; it++) {
        const int cur = it & 1;
        if (it + 1 < NIT) {
            const int k0 = (it + 1) * 16;
            p0 = *(const float4*)(P + k0);
            p1 = *(const float4*)(P + k0 + 4);
            p0.x *= inv; p0.y *= inv; p0.z *= inv; p0.w *= inv;
            p1.x *= inv; p1.y *= inv; p1.z *= inv; p1.w *= inv;
            *(float4*)(P + k0)     = p0;
            *(float4*)(P + k0 + 4) = p1;
            ve = *(const float2*)(Vbase + (size_t)(k0 + 2 * vu) * D_);
            vo = *(const float2*)(Vbase + (size_t)(k0 + 2 * vu + 1) * D_);
        }
        {
            uint32_t af[2][4];
#pragma unroll
            for (int i = 0; i < 2; i++) {
                af[i][0] = Ps[cur][kl    ][mg + i * 16];
                af[i][1] = Ps[cur][kl    ][mg + i * 16 + 8];
                af[i][2] = Ps[cur][kl + 4][mg + i * 16];
                af[i][3] = Ps[cur][kl + 4][mg + i * 16 + 8];
            }
            uint32_t bf[4][2];
#pragma unroll
            for (int j = 0; j < 4; j++) {
                bf[j][0] = Vs[cur][kl    ][ng + j * 8];
                bf[j][1] = Vs[cur][kl + 4][ng + j * 8];
            }
#pragma unroll
            for (int j = 0; j < 4; j++)
#pragma unroll
                for (int i = 0; i < 2; i++)
                    mma_f16(acc[i][j], af[i][0], af[i][1], af[i][2], af[i][3],
                            bf[j][0], bf[j][1]);
        }
        if (it + 1 < NIT) {
            const int nxt = cur ^ 1;
            STS8H(Ps[nxt], kkb, prow, p0, p1);
            Vs[nxt][vu][vn]     = f2h2(ve.x, vo.x);
            Vs[nxt][vu][vn + 1] = f2h2(ve.y, vo.y);
            __syncthreads();
        }
    }

    float* Cc = ctx + (size_t)zb * S_ * D_ + (size_t)zh * DK_;
    const int row0 = bm + wm * 32 + (lane >> 2);
    const int col0 = wn * 32 + (lane & 3) * 2;
#pragma unroll
    for (int i = 0; i < 2; i++) {
#pragma unroll
        for (int j = 0; j < 4; j++) {
            const int r = row0 + i * 16;
            const int c = col0 + j * 8;
            float2 lo, hi;
            lo.x = acc[i][j][0]; lo.y = acc[i][j][1];
            hi.x = acc[i][j][2]; hi.y = acc[i][j][3];
            *(float2*)&Cc[(size_t)r * D_ + c]       = lo;
            *(float2*)&Cc[(size_t)(r + 8) * D_ + c] = hi;
        }
    }
}

// ---------------- launch ----------------
extern "C" void kernel_launch(void* const* d_in, const int* in_sizes, int n_in,
                              void* d_out, int out_size)
{
    const float* query = (const float*)d_in[0];
    const float* key   = (const float*)d_in[1];
    const float* value = (const float*)d_in[2];
    const float* Wq    = (const float*)d_in[3];
    const float* bq    = (const float*)d_in[4];
    const float* Wk    = (const float*)d_in[5];
    const float* bk    = (const float*)d_in[6];
    const float* Wv    = (const float*)d_in[7];
    const float* bv    = (const float*)d_in[8];
    const float* Wo    = (const float*)d_in[9];
    const float* bo    = (const float*)d_in[10];

    float* out  = (float*)d_out;                          // (B,S,D)
    float* attn = out + (size_t)B_ * S_ * D_;             // (B,H,S,S)

    float *q, *k, *v, *ctx, *part;
    cudaGetSymbolAddress((void**)&q,    g_q);
    cudaGetSymbolAddress((void**)&k,    g_k);
    cudaGetSymbolAddress((void**)&v,    g_v);
    cudaGetSymbolAddress((void**)&ctx,  g_ctx);
    cudaGetSymbolAddress((void**)&part, g_partial);

    // Projections: C[4096,1024] = X @ W^T + b
    dim3 pgrid(D_ / 128, (B_ * S_) / 128, 1);
    gemm_f16<D_, true, false><<<pgrid, 256>>>(query, Wq, bq, q,
        D_, D_, D_, 0, 0, 0, 0, 0, 0, 1.f, nullptr);
    gemm_f16<D_, true, false><<<pgrid, 256>>>(key, Wk, bk, k,
        D_, D_, D_, 0, 0, 0, 0, 0, 0, 1.f, nullptr);
    gemm_f16<D_, true, false><<<pgrid, 256>>>(value, Wv, bv, v,
        D_, D_, D_, 0, 0, 0, 0, 0, 0, 1.f, nullptr);

    // QK^T -> exp(scores) + row partial sums
    dim3 qkgrid(S_ / 128, S_ / 128, B_ * H_);
    gemm_f16<DK_, false, true><<<qkgrid, 256>>>(q, k, nullptr, attn,
        D_, D_, S_,
        (size_t)S_ * D_, DK_,
        (size_t)S_ * D_, DK_,
        (size_t)H_ * S_ * S_, (size_t)S_ * S_,
        0.125f, part);

    // normalize attn in place + ctx = P @ V
    dim3 pvgrid(S_ / 128, B_ * H_);
    pv_f16<<<pvgrid, 256>>>(attn, v, ctx, part);

    // output projection
    gemm_f16<D_, true, false><<<pgrid, 256>>>(ctx, Wo, bo, out,
        D_, D_, D_, 0, 0, 0, 0, 0, 0, 1.f, nullptr);
}

// round 10
// speedup vs baseline: 1.7239x; 1.0575x over previous
#include <cuda_runtime.h>
#include <cuda_fp16.h>
#include <math.h>
#include <stdint.h>
#include <type_traits>

// Problem constants
#define B_ 2
#define S_ 2048
#define D_ 1024
#define H_ 16
#define DK_ 64

// ---------------- scratch (no cudaMalloc allowed) ----------------
__device__ __half g_qh[(size_t)B_ * S_ * D_];
__device__ __half g_kh[(size_t)B_ * S_ * D_];
__device__ __half g_vh[(size_t)B_ * S_ * D_];
__device__ __half g_ctxh[(size_t)B_ * S_ * D_];
// per-row exp partial sums: [z][row][16 bn-tiles * 4 wn] = 64 partials/row
__device__ float g_partial[(size_t)B_ * H_ * S_ * 64];

// ---------------- FP16 helpers ----------------
__device__ __forceinline__ uint32_t f2h2(float lo, float hi) {
    __half2 h = __floats2half2_rn(lo, hi);
    return *(uint32_t*)&h;
}

__device__ __forceinline__ void mma_f16(float c[4],
    uint32_t a0, uint32_t a1, uint32_t a2, uint32_t a3,
    uint32_t b0, uint32_t b1)
{
    asm volatile(
        "mma.sync.aligned.m16n8k16.row.col.f32.f16.f16.f32 "
        "{%0,%1,%2,%3}, {%4,%5,%6,%7}, {%8,%9}, {%0,%1,%2,%3};"
        : "+f"(c[0]), "+f"(c[1]), "+f"(c[2]), "+f"(c[3])
        : "r"(a0), "r"(a1), "r"(a2), "r"(a3), "r"(b0), "r"(b1));
}

// smem tile word = 2 consecutive-k fp16
#define STS8H(s, kkb, r, v0, v1) do { \
    (s)[(kkb) + 0][r] = f2h2((v0).x, (v0).y); \
    (s)[(kkb) + 1][r] = f2h2((v0).z, (v0).w); \
    (s)[(kkb) + 2][r] = f2h2((v1).x, (v1).y); \
    (s)[(kkb) + 3][r] = f2h2((v1).z, (v1).w); \
} while (0)

#define STS8HU(s, kkb, r, u) do { \
    (s)[(kkb) + 0][r] = (u).x; \
    (s)[(kkb) + 1][r] = (u).y; \
    (s)[(kkb) + 2][r] = (u).z; \
    (s)[(kkb) + 3][r] = (u).w; \
} while (0)

// ================= generic FP16-operand NT GEMM =================
// C[M,N] = scale * A[M,K] @ B[N,K]^T (+ bias[N]), or exp-epilogue for QK.
// Block 128x128, 256 threads (8 warps as 2x4 grid of 64x32 warp tiles), BK=16.
// TA/TB in {float, __half} (fp32 converted in loader); TC in {float, __half}.
template<int KDIM, class TA, class TB, class TC, bool HAS_BIAS, bool EXP_MODE>
__global__ __launch_bounds__(256, 2) void gemm_h(
    const TA* __restrict__ A, const TB* __restrict__ Bm,
    const float* __restrict__ bias, TC* __restrict__ C,
    int lda, int ldb, int ldc,
    size_t aB, size_t aH, size_t bB, size_t bH, size_t cB, size_t cH,
    float scale, float* __restrict__ partial)
{
    constexpr bool A_HALF = std::is_same<TA, __half>::value;
    constexpr bool B_HALF = std::is_same<TB, __half>::value;
    constexpr bool OUT_HALF = std::is_same<TC, __half>::value;

    __shared__ uint32_t As[2][8][136];
    __shared__ uint32_t Bs[2][8][136];

    const int tid  = threadIdx.x;
    const int lane = tid & 31;
    const int wid  = tid >> 5;
    const int wm   = wid & 1;            // 0..1 -> 64-row half
    const int wn   = wid >> 1;           // 0..3 -> 32-col quarter
    const int bm   = blockIdx.y * 128;
    const int bn   = blockIdx.x * 128;
    const int z    = blockIdx.z;
    const int zb   = z >> 4, zh = z & 15;

    // R4/R8 loader mapping (LDG-optimal)
    const int arow = tid >> 1;           // 0..127
    const int ak   = (tid & 1) * 8;      // k offset 0 or 8
    const int kkb  = (tid & 1) * 4;      // pair offset 0 or 4

    const TA* Ap = A + zb * aB + zh * aH + (size_t)(bm + arow) * lda + ak;
    const TB* Bp = Bm + zb * bB + zh * bH + (size_t)(bn + arow) * ldb + ak;

    float acc[4][4][4];
#pragma unroll
    for (int i = 0; i < 4; i++)
#pragma unroll
        for (int j = 0; j < 4; j++)
#pragma unroll
            for (int e = 0; e < 4; e++) acc[i][j][e] = 0.f;

    float4 a0, a1, b0, b1;
    uint4  ahv, bhv;
    if constexpr (A_HALF) ahv = *(const uint4*)(Ap);
    else { a0 = *(const float4*)(Ap); a1 = *(const float4*)(Ap + 4); }
    if constexpr (B_HALF) bhv = *(const uint4*)(Bp);
    else { b0 = *(const float4*)(Bp); b1 = *(const float4*)(Bp + 4); }

    if constexpr (A_HALF) STS8HU(As[0], kkb, arow, ahv);
    else                  STS8H(As[0], kkb, arow, a0, a1);
    if constexpr (B_HALF) STS8HU(Bs[0], kkb, arow, bhv);
    else                  STS8H(Bs[0], kkb, arow, b0, b1);
    __syncthreads();

    const int NIT = KDIM / 16;
    const int mg  = wm * 64 + (lane >> 2);
    const int ng  = wn * 32 + (lane >> 2);
    const int kl  = lane & 3;

    for (int it = 0; it < NIT; it++) {
        const int cur = it & 1;
        if (it + 1 < NIT) {
            const int k0 = (it + 1) * 16;
            if constexpr (A_HALF) ahv = *(const uint4*)(Ap + k0);
            else { a0 = *(const float4*)(Ap + k0); a1 = *(const float4*)(Ap + k0 + 4); }
            if constexpr (B_HALF) bhv = *(const uint4*)(Bp + k0);
            else { b0 = *(const float4*)(Bp + k0); b1 = *(const float4*)(Bp + k0 + 4); }
        }
        {
            uint32_t af[4][4];
#pragma unroll
            for (int i = 0; i < 4; i++) {
                af[i][0] = As[cur][kl    ][mg + i * 16];
                af[i][1] = As[cur][kl    ][mg + i * 16 + 8];
                af[i][2] = As[cur][kl + 4][mg + i * 16];
                af[i][3] = As[cur][kl + 4][mg + i * 16 + 8];
            }
            uint32_t bf[4][2];
#pragma unroll
            for (int j = 0; j < 4; j++) {
                bf[j][0] = Bs[cur][kl    ][ng + j * 8];
                bf[j][1] = Bs[cur][kl + 4][ng + j * 8];
            }
#pragma unroll
            for (int j = 0; j < 4; j++)
#pragma unroll
                for (int i = 0; i < 4; i++)
                    mma_f16(acc[i][j], af[i][0], af[i][1], af[i][2], af[i][3],
                            bf[j][0], bf[j][1]);
        }
        if (it + 1 < NIT) {
            const int nxt = cur ^ 1;
            if constexpr (A_HALF) STS8HU(As[nxt], kkb, arow, ahv);
            else                  STS8H(As[nxt], kkb, arow, a0, a1);
            if constexpr (B_HALF) STS8HU(Bs[nxt], kkb, arow, bhv);
            else                  STS8H(Bs[nxt], kkb, arow, b0, b1);
            __syncthreads();
        }
    }

    // epilogue
    const int rl   = wm * 64 + (lane >> 2);
    const int col0 = bn + wn * 32 + (lane & 3) * 2;

    if constexpr (EXP_MODE) {
        float* Cp = (float*)C + zb * cB + zh * cH;
#pragma unroll
        for (int i = 0; i < 4; i++) {
            const int rlo = bm + rl + i * 16;
            const int rhi = rlo + 8;
            float pl = 0.f, ph = 0.f;
#pragma unroll
            for (int j = 0; j < 4; j++) {
                float e0 = __expf(acc[i][j][0] * scale);
                float e1 = __expf(acc[i][j][1] * scale);
                float e2 = __expf(acc[i][j][2] * scale);
                float e3 = __expf(acc[i][j][3] * scale);
                float2 lo; lo.x = e0; lo.y = e1;
                float2 hi; hi.x = e2; hi.y = e3;
                *(float2*)&Cp[(size_t)rlo * ldc + col0 + j * 8] = lo;
                *(float2*)&Cp[(size_t)rhi * ldc + col0 + j * 8] = hi;
                pl += e0 + e1;
                ph += e2 + e3;
            }
            pl += __shfl_xor_sync(0xffffffffu, pl, 1);
            pl += __shfl_xor_sync(0xffffffffu, pl, 2);
            ph += __shfl_xor_sync(0xffffffffu, ph, 1);
            ph += __shfl_xor_sync(0xffffffffu, ph, 2);
            if ((lane & 3) == 0) {
                partial[((size_t)z * S_ + rlo) * 64 + blockIdx.x * 4 + wn] = pl;
                partial[((size_t)z * S_ + rhi) * 64 + blockIdx.x * 4 + wn] = ph;
            }
        }
    } else {
        float2 bvj[4];
        if constexpr (HAS_BIAS) {
#pragma unroll
            for (int j = 0; j < 4; j++)
                bvj[j] = *(const float2*)&bias[col0 + j * 8];
        }
        TC* Cp = C + zb * cB + zh * cH;
#pragma unroll
        for (int i = 0; i < 4; i++) {
#pragma unroll
            for (int j = 0; j < 4; j++) {
                const int r = bm + rl + i * 16;
                const int c = col0 + j * 8;
                float lx = acc[i][j][0] * scale, ly = acc[i][j][1] * scale;
                float hx = acc[i][j][2] * scale, hy = acc[i][j][3] * scale;
                if constexpr (HAS_BIAS) {
                    lx += bvj[j].x; ly += bvj[j].y;
                    hx += bvj[j].x; hy += bvj[j].y;
                }
                if constexpr (OUT_HALF) {
                    *(uint32_t*)&Cp[(size_t)r * ldc + c]       = f2h2(lx, ly);
                    *(uint32_t*)&Cp[(size_t)(r + 8) * ldc + c] = f2h2(hx, hy);
                } else {
                    float2 lo; lo.x = lx; lo.y = ly;
                    float2 hi; hi.x = hx; hi.y = hy;
                    *(float2*)&Cp[(size_t)r * ldc + c]       = lo;
                    *(float2*)&Cp[(size_t)(r + 8) * ldc + c] = hi;
                }
            }
        }
    }
}

// ================= PV: normalize attn in place + ctx = P @ V =================
// Block 128(M)x64(N), 256 threads (8 warps as 4x2 grid of 32x32 warp tiles), BK=16.
// P fp32 (attn in/out), V fp16, ctx fp16 out.
__global__ __launch_bounds__(256, 2) void pv_h(
    float* __restrict__ attn, const __half* __restrict__ Vg,
    __half* __restrict__ ctx, const float* __restrict__ partial)
{
    __shared__ uint32_t Ps[2][8][136];
    __shared__ uint32_t Vs[2][8][72];
    __shared__ float s_inv[128];

    const int tid  = threadIdx.x;
    const int lane = tid & 31;
    const int wid  = tid >> 5;
    const int wm   = wid & 3;         // 32-row quarter
    const int wn   = wid >> 2;        // 32-col half
    const int bm   = blockIdx.x * 128;
    const int z    = blockIdx.y;
    const int zb   = z >> 4, zh = z & 15;

    // prologue: per-row inverse sums (64 partials per row)
    {
        const int r = tid >> 1;
        const float* pp = partial + ((size_t)z * S_ + bm + r) * 64 + (tid & 1) * 32;
        float s = 0.f;
#pragma unroll
        for (int f = 0; f < 8; f++) {
            float4 u = ((const float4*)pp)[f];
            s += (u.x + u.y) + (u.z + u.w);
        }
        s += __shfl_xor_sync(0xffffffffu, s, 1);
        if (!(tid & 1)) s_inv[r] = 1.f / s;
    }
    __syncthreads();

    const int prow = tid >> 1;
    const int pk   = (tid & 1) * 8;
    const int kkb  = (tid & 1) * 4;
    float* P = attn + (size_t)z * S_ * S_ + (size_t)(bm + prow) * S_ + pk;
    const float inv = s_inv[prow];

    // V loader: warp u loads V rows 2u,2u+1 (fp16); lane covers n = 2*lane..2*lane+1
    const int vu = wid;
    const int vn = lane * 2;
    const __half* Vbase = Vg + (size_t)zb * S_ * D_ + (size_t)zh * DK_ + vn;

    float acc[2][4][4];
#pragma unroll
    for (int i = 0; i < 2; i++)
#pragma unroll
        for (int j = 0; j < 4; j++)
#pragma unroll
            for (int e = 0; e < 4; e++) acc[i][j][e] = 0.f;

    float4 p0, p1;
    __half2 ve, vo;
    p0 = *(const float4*)(P);
    p1 = *(const float4*)(P + 4);
    p0.x *= inv; p0.y *= inv; p0.z *= inv; p0.w *= inv;
    p1.x *= inv; p1.y *= inv; p1.z *= inv; p1.w *= inv;
    *(float4*)(P)     = p0;    // final normalized attn
    *(float4*)(P + 4) = p1;
    ve = *(const __half2*)(Vbase + (size_t)(2 * vu) * D_);
    vo = *(const __half2*)(Vbase + (size_t)(2 * vu + 1) * D_);
    STS8H(Ps[0], kkb, prow, p0, p1);
    {
        __half2 w0 = __lows2half2(ve, vo);    // (v[2u][n], v[2u+1][n])
        __half2 w1 = __highs2half2(ve, vo);   // (v[2u][n+1], v[2u+1][n+1])
        Vs[0][vu][vn]     = *(uint32_t*)&w0;
        Vs[0][vu][vn + 1] = *(uint32_t*)&w1;
    }
    __syncthreads();

    const int NIT = S_ / 16;
    const int mg  = wm * 32 + (lane >> 2);
    const int ng  = wn * 32 + (lane >> 2);
    const int kl  = lane & 3;

    for (int it = 0; it < NIT; it++) {
        const int cur = it & 1;
        if (it + 1 < NIT) {
            const int k0 = (it + 1) * 16;
            p0 = *(const float4*)(P + k0);
            p1 = *(const float4*)(P + k0 + 4);
            p0.x *= inv; p0.y *= inv; p0.z *= inv; p0.w *= inv;
            p1.x *= inv; p1.y *= inv; p1.z *= inv; p1.w *= inv;
            *(float4*)(P + k0)     = p0;
            *(float4*)(P + k0 + 4) = p1;
            ve = *(const __half2*)(Vbase + (size_t)(k0 + 2 * vu) * D_);
            vo = *(const __half2*)(Vbase + (size_t)(k0 + 2 * vu + 1) * D_);
        }
        {
            uint32_t af[2][4];
#pragma unroll
            for (int i = 0; i < 2; i++) {
                af[i][0] = Ps[cur][kl    ][mg + i * 16];
                af[i][1] = Ps[cur][kl    ][mg + i * 16 + 8];
                af[i][2] = Ps[cur][kl + 4][mg + i * 16];
                af[i][3] = Ps[cur][kl + 4][mg + i * 16 + 8];
            }
            uint32_t bf[4][2];
#pragma unroll
            for (int j = 0; j < 4; j++) {
                bf[j][0] = Vs[cur][kl    ][ng + j * 8];
                bf[j][1] = Vs[cur][kl + 4][ng + j * 8];
            }
#pragma unroll
            for (int j = 0; j < 4; j++)
#pragma unroll
                for (int i = 0; i < 2; i++)
                    mma_f16(acc[i][j], af[i][0], af[i][1], af[i][2], af[i][3],
                            bf[j][0], bf[j][1]);
        }
        if (it + 1 < NIT) {
            const int nxt = cur ^ 1;
            STS8H(Ps[nxt], kkb, prow, p0, p1);
            __half2 w0 = __lows2half2(ve, vo);
            __half2 w1 = __highs2half2(ve, vo);
            Vs[nxt][vu][vn]     = *(uint32_t*)&w0;
            Vs[nxt][vu][vn + 1] = *(uint32_t*)&w1;
            __syncthreads();
        }
    }

    __half* Cc = ctx + (size_t)zb * S_ * D_ + (size_t)zh * DK_;
    const int row0 = bm + wm * 32 + (lane >> 2);
    const int col0 = wn * 32 + (lane & 3) * 2;
#pragma unroll
    for (int i = 0; i < 2; i++) {
#pragma unroll
        for (int j = 0; j < 4; j++) {
            const int r = row0 + i * 16;
            const int c = col0 + j * 8;
            *(uint32_t*)&Cc[(size_t)r * D_ + c]       = f2h2(acc[i][j][0], acc[i][j][1]);
            *(uint32_t*)&Cc[(size_t)(r + 8) * D_ + c] = f2h2(acc[i][j][2], acc[i][j][3]);
        }
    }
}

// ---------------- launch ----------------
extern "C" void kernel_launch(void* const* d_in, const int* in_sizes, int n_in,
                              void* d_out, int out_size)
{
    const float* query = (const float*)d_in[0];
    const float* key   = (const float*)d_in[1];
    const float* value = (const float*)d_in[2];
    const float* Wq    = (const float*)d_in[3];
    const float* bq    = (const float*)d_in[4];
    const float* Wk    = (const float*)d_in[5];
    const float* bk    = (const float*)d_in[6];
    const float* Wv    = (const float*)d_in[7];
    const float* bv    = (const float*)d_in[8];
    const float* Wo    = (const float*)d_in[9];
    const float* bo    = (const float*)d_in[10];

    float* out  = (float*)d_out;                          // (B,S,D)
    float* attn = out + (size_t)B_ * S_ * D_;             // (B,H,S,S)

    __half *qh, *kh, *vh, *ctxh;
    float *part;
    cudaGetSymbolAddress((void**)&qh,   g_qh);
    cudaGetSymbolAddress((void**)&kh,   g_kh);
    cudaGetSymbolAddress((void**)&vh,   g_vh);
    cudaGetSymbolAddress((void**)&ctxh, g_ctxh);
    cudaGetSymbolAddress((void**)&part, g_partial);

    // Projections: q/k/v = X @ W^T + b  (fp32 in, fp16 out)
    dim3 pgrid(D_ / 128, (B_ * S_) / 128, 1);
    gemm_h<D_, float, float, __half, true, false><<<pgrid, 256>>>(query, Wq, bq, qh,
        D_, D_, D_, 0, 0, 0, 0, 0, 0, 1.f, nullptr);
    gemm_h<D_, float, float, __half, true, false><<<pgrid, 256>>>(key, Wk, bk, kh,
        D_, D_, D_, 0, 0, 0, 0, 0, 0, 1.f, nullptr);
    gemm_h<D_, float, float, __half, true, false><<<pgrid, 256>>>(value, Wv, bv, vh,
        D_, D_, D_, 0, 0, 0, 0, 0, 0, 1.f, nullptr);

    // QK^T -> exp(scores) + row partial sums  (fp16 in, fp32 attn out)
    dim3 qkgrid(S_ / 128, S_ / 128, B_ * H_);
    gemm_h<DK_, __half, __half, float, false, true><<<qkgrid, 256>>>(qh, kh, nullptr, attn,
        D_, D_, S_,
        (size_t)S_ * D_, (size_t)DK_,
        (size_t)S_ * D_, (size_t)DK_,
        (size_t)H_ * S_ * S_, (size_t)S_ * S_,
        0.125f, part);

    // normalize attn in place + ctx = P @ V  (fp16 V, fp16 ctx)
    dim3 pvgrid(S_ / 128, B_ * H_);
    pv_h<<<pvgrid, 256>>>(attn, vh, ctxh, part);

    // output projection  (fp16 ctx in, fp32 out)
    gemm_h<D_, __half, float, float, true, false><<<pgrid, 256>>>(ctxh, Wo, bo, out,
        D_, D_, D_, 0, 0, 0, 0, 0, 0, 1.f, nullptr);
}

// round 11
// speedup vs baseline: 1.9557x; 1.1345x over previous
#include <cuda_runtime.h>
#include <cuda_fp16.h>
#include <math.h>
#include <stdint.h>
#include <type_traits>

// Problem constants
#define B_ 2
#define S_ 2048
#define D_ 1024
#define H_ 16
#define DK_ 64

// ---------------- scratch (no cudaMalloc allowed) ----------------
__device__ __half g_qh[(size_t)B_ * S_ * D_];
__device__ __half g_kh[(size_t)B_ * S_ * D_];
__device__ __half g_vh[(size_t)B_ * S_ * D_];
__device__ __half g_ctxh[(size_t)B_ * S_ * D_];
// fp16 copies of inputs / weights
__device__ __half g_xq[(size_t)B_ * S_ * D_];
__device__ __half g_xk[(size_t)B_ * S_ * D_];
__device__ __half g_xv[(size_t)B_ * S_ * D_];
__device__ __half g_wq[(size_t)D_ * D_];
__device__ __half g_wk[(size_t)D_ * D_];
__device__ __half g_wv[(size_t)D_ * D_];
__device__ __half g_wo[(size_t)D_ * D_];
// fp16 exp(scores) scratch
__device__ __half g_ph[(size_t)B_ * H_ * S_ * S_];
// per-row exp partial sums: [z][row][16 bn-tiles * 4 wn] = 64 partials/row
__device__ float g_partial[(size_t)B_ * H_ * S_ * 64];

// ---------------- FP16 helpers ----------------
__device__ __forceinline__ uint32_t f2h2(float lo, float hi) {
    __half2 h = __floats2half2_rn(lo, hi);
    return *(uint32_t*)&h;
}

__device__ __forceinline__ void mma_f16(float c[4],
    uint32_t a0, uint32_t a1, uint32_t a2, uint32_t a3,
    uint32_t b0, uint32_t b1)
{
    asm volatile(
        "mma.sync.aligned.m16n8k16.row.col.f32.f16.f16.f32 "
        "{%0,%1,%2,%3}, {%4,%5,%6,%7}, {%8,%9}, {%0,%1,%2,%3};"
        : "+f"(c[0]), "+f"(c[1]), "+f"(c[2]), "+f"(c[3])
        : "r"(a0), "r"(a1), "r"(a2), "r"(a3), "r"(b0), "r"(b1));
}

#define STS8H(s, kkb, r, v0, v1) do { \
    (s)[(kkb) + 0][r] = f2h2((v0).x, (v0).y); \
    (s)[(kkb) + 1][r] = f2h2((v0).z, (v0).w); \
    (s)[(kkb) + 2][r] = f2h2((v1).x, (v1).y); \
    (s)[(kkb) + 3][r] = f2h2((v1).z, (v1).w); \
} while (0)

#define STS8HU(s, kkb, r, u) do { \
    (s)[(kkb) + 0][r] = (u).x; \
    (s)[(kkb) + 1][r] = (u).y; \
    (s)[(kkb) + 2][r] = (u).z; \
    (s)[(kkb) + 3][r] = (u).w; \
} while (0)

// ================= fp32 -> fp16 conversion (inputs + weights) =================
// 8192 blocks x 256 threads x 8 elems: segs q,k,v (2048 blocks each), 4 W (512 each)
__global__ __launch_bounds__(256) void to_half7(
    const float* __restrict__ s0, const float* __restrict__ s1, const float* __restrict__ s2,
    const float* __restrict__ s3, const float* __restrict__ s4, const float* __restrict__ s5,
    const float* __restrict__ s6,
    __half* __restrict__ d0, __half* __restrict__ d1, __half* __restrict__ d2,
    __half* __restrict__ d3, __half* __restrict__ d4, __half* __restrict__ d5,
    __half* __restrict__ d6)
{
    int b = blockIdx.x;
    const float* src; __half* dst; int off;
    if      (b < 2048) { src = s0; dst = d0; off = b; }
    else if (b < 4096) { src = s1; dst = d1; off = b - 2048; }
    else if (b < 6144) { src = s2; dst = d2; off = b - 4096; }
    else {
        int w = (b - 6144) >> 9;
        off = (b - 6144) & 511;
        src = (w == 0) ? s3 : (w == 1) ? s4 : (w == 2) ? s5 : s6;
        dst = (w == 0) ? d3 : (w == 1) ? d4 : (w == 2) ? d5 : d6;
    }
    size_t base = (size_t)off * 2048 + threadIdx.x * 8;
    float4 u0 = *(const float4*)(src + base);
    float4 u1 = *(const float4*)(src + base + 4);
    uint4 o;
    o.x = f2h2(u0.x, u0.y); o.y = f2h2(u0.z, u0.w);
    o.z = f2h2(u1.x, u1.y); o.w = f2h2(u1.z, u1.w);
    *(uint4*)(dst + base) = o;
}

// ================= generic FP16-operand NT GEMM =================
// Block 128x128, 256 threads (8 warps as 2x4 grid of 64x32 warp tiles), BK=16.
template<int KDIM, class TA, class TB, class TC, bool HAS_BIAS, bool EXP_MODE>
__global__ __launch_bounds__(256, 2) void gemm_h(
    const TA* __restrict__ A, const TB* __restrict__ Bm,
    const float* __restrict__ bias, TC* __restrict__ C,
    int lda, int ldb, int ldc,
    size_t aB, size_t aH, size_t bB, size_t bH, size_t cB, size_t cH,
    float scale, float* __restrict__ partial)
{
    constexpr bool A_HALF = std::is_same<TA, __half>::value;
    constexpr bool B_HALF = std::is_same<TB, __half>::value;
    constexpr bool OUT_HALF = std::is_same<TC, __half>::value;

    __shared__ uint32_t As[2][8][136];
    __shared__ uint32_t Bs[2][8][136];

    const int tid  = threadIdx.x;
    const int lane = tid & 31;
    const int wid  = tid >> 5;
    const int wm   = wid & 1;
    const int wn   = wid >> 1;
    const int bm   = blockIdx.y * 128;
    const int bn   = blockIdx.x * 128;
    const int z    = blockIdx.z;
    const int zb   = z >> 4, zh = z & 15;

    const int arow = tid >> 1;
    const int ak   = (tid & 1) * 8;
    const int kkb  = (tid & 1) * 4;

    const TA* Ap = A + zb * aB + zh * aH + (size_t)(bm + arow) * lda + ak;
    const TB* Bp = Bm + zb * bB + zh * bH + (size_t)(bn + arow) * ldb + ak;

    float acc[4][4][4];
#pragma unroll
    for (int i = 0; i < 4; i++)
#pragma unroll
        for (int j = 0; j < 4; j++)
#pragma unroll
            for (int e = 0; e < 4; e++) acc[i][j][e] = 0.f;

    float4 a0, a1, b0, b1;
    uint4  ahv, bhv;
    if constexpr (A_HALF) ahv = *(const uint4*)(Ap);
    else { a0 = *(const float4*)(Ap); a1 = *(const float4*)(Ap + 4); }
    if constexpr (B_HALF) bhv = *(const uint4*)(Bp);
    else { b0 = *(const float4*)(Bp); b1 = *(const float4*)(Bp + 4); }

    if constexpr (A_HALF) STS8HU(As[0], kkb, arow, ahv);
    else                  STS8H(As[0], kkb, arow, a0, a1);
    if constexpr (B_HALF) STS8HU(Bs[0], kkb, arow, bhv);
    else                  STS8H(Bs[0], kkb, arow, b0, b1);
    __syncthreads();

    const int NIT = KDIM / 16;
    const int mg  = wm * 64 + (lane >> 2);
    const int ng  = wn * 32 + (lane >> 2);
    const int kl  = lane & 3;

    for (int it = 0; it < NIT; it++) {
        const int cur = it & 1;
        if (it + 1 < NIT) {
            const int k0 = (it + 1) * 16;
            if constexpr (A_HALF) ahv = *(const uint4*)(Ap + k0);
            else { a0 = *(const float4*)(Ap + k0); a1 = *(const float4*)(Ap + k0 + 4); }
            if constexpr (B_HALF) bhv = *(const uint4*)(Bp + k0);
            else { b0 = *(const float4*)(Bp + k0); b1 = *(const float4*)(Bp + k0 + 4); }
        }
        {
            uint32_t af[4][4];
#pragma unroll
            for (int i = 0; i < 4; i++) {
                af[i][0] = As[cur][kl    ][mg + i * 16];
                af[i][1] = As[cur][kl    ][mg + i * 16 + 8];
                af[i][2] = As[cur][kl + 4][mg + i * 16];
                af[i][3] = As[cur][kl + 4][mg + i * 16 + 8];
            }
            uint32_t bf[4][2];
#pragma unroll
            for (int j = 0; j < 4; j++) {
                bf[j][0] = Bs[cur][kl    ][ng + j * 8];
                bf[j][1] = Bs[cur][kl + 4][ng + j * 8];
            }
#pragma unroll
            for (int j = 0; j < 4; j++)
#pragma unroll
                for (int i = 0; i < 4; i++)
                    mma_f16(acc[i][j], af[i][0], af[i][1], af[i][2], af[i][3],
                            bf[j][0], bf[j][1]);
        }
        if (it + 1 < NIT) {
            const int nxt = cur ^ 1;
            if constexpr (A_HALF) STS8HU(As[nxt], kkb, arow, ahv);
            else                  STS8H(As[nxt], kkb, arow, a0, a1);
            if constexpr (B_HALF) STS8HU(Bs[nxt], kkb, arow, bhv);
            else                  STS8H(Bs[nxt], kkb, arow, b0, b1);
            __syncthreads();
        }
    }

    // epilogue
    const int rl   = wm * 64 + (lane >> 2);
    const int col0 = bn + wn * 32 + (lane & 3) * 2;

    if constexpr (EXP_MODE) {
        // write exp(scale*s) as fp16 to scratch; fp32 row partial sums
        TC* Cp = C + zb * cB + zh * cH;
#pragma unroll
        for (int i = 0; i < 4; i++) {
            const int rlo = bm + rl + i * 16;
            const int rhi = rlo + 8;
            float pl = 0.f, ph = 0.f;
#pragma unroll
            for (int j = 0; j < 4; j++) {
                float e0 = __expf(acc[i][j][0] * scale);
                float e1 = __expf(acc[i][j][1] * scale);
                float e2 = __expf(acc[i][j][2] * scale);
                float e3 = __expf(acc[i][j][3] * scale);
                if constexpr (OUT_HALF) {
                    *(uint32_t*)&Cp[(size_t)rlo * ldc + col0 + j * 8] = f2h2(e0, e1);
                    *(uint32_t*)&Cp[(size_t)rhi * ldc + col0 + j * 8] = f2h2(e2, e3);
                } else {
                    float2 lo; lo.x = e0; lo.y = e1;
                    float2 hi; hi.x = e2; hi.y = e3;
                    *(float2*)&Cp[(size_t)rlo * ldc + col0 + j * 8] = lo;
                    *(float2*)&Cp[(size_t)rhi * ldc + col0 + j * 8] = hi;
                }
                pl += e0 + e1;
                ph += e2 + e3;
            }
            pl += __shfl_xor_sync(0xffffffffu, pl, 1);
            pl += __shfl_xor_sync(0xffffffffu, pl, 2);
            ph += __shfl_xor_sync(0xffffffffu, ph, 1);
            ph += __shfl_xor_sync(0xffffffffu, ph, 2);
            if ((lane & 3) == 0) {
                partial[((size_t)z * S_ + rlo) * 64 + blockIdx.x * 4 + wn] = pl;
                partial[((size_t)z * S_ + rhi) * 64 + blockIdx.x * 4 + wn] = ph;
            }
        }
    } else {
        float2 bvj[4];
        if constexpr (HAS_BIAS) {
#pragma unroll
            for (int j = 0; j < 4; j++)
                bvj[j] = *(const float2*)&bias[col0 + j * 8];
        }
        TC* Cp = C + zb * cB + zh * cH;
#pragma unroll
        for (int i = 0; i < 4; i++) {
#pragma unroll
            for (int j = 0; j < 4; j++) {
                const int r = bm + rl + i * 16;
                const int c = col0 + j * 8;
                float lx = acc[i][j][0] * scale, ly = acc[i][j][1] * scale;
                float hx = acc[i][j][2] * scale, hy = acc[i][j][3] * scale;
                if constexpr (HAS_BIAS) {
                    lx += bvj[j].x; ly += bvj[j].y;
                    hx += bvj[j].x; hy += bvj[j].y;
                }
                if constexpr (OUT_HALF) {
                    *(uint32_t*)&Cp[(size_t)r * ldc + c]       = f2h2(lx, ly);
                    *(uint32_t*)&Cp[(size_t)(r + 8) * ldc + c] = f2h2(hx, hy);
                } else {
                    float2 lo; lo.x = lx; lo.y = ly;
                    float2 hi; hi.x = hx; hi.y = hy;
                    *(float2*)&Cp[(size_t)r * ldc + c]       = lo;
                    *(float2*)&Cp[(size_t)(r + 8) * ldc + c] = hi;
                }
            }
        }
    }
}

// ================= PV: write normalized attn (fp32) + ctx = inv * (expP @ V) ===
// Block 128(M)x64(N), 256 threads (8 warps as 4x2 grid of 32x32 warp tiles), BK=16.
// Reads fp16 exp scratch, writes fp32 attn once, feeds raw exp to MMA,
// scales ctx by per-row inv in the epilogue.
__global__ __launch_bounds__(256, 2) void pv_h(
    const __half* __restrict__ Pexp, float* __restrict__ attn,
    const __half* __restrict__ Vg,
    __half* __restrict__ ctx, const float* __restrict__ partial)
{
    __shared__ uint32_t Ps[2][8][136];
    __shared__ uint32_t Vs[2][8][72];
    __shared__ float s_inv[128];

    const int tid  = threadIdx.x;
    const int lane = tid & 31;
    const int wid  = tid >> 5;
    const int wm   = wid & 3;
    const int wn   = wid >> 2;
    const int bm   = blockIdx.x * 128;
    const int z    = blockIdx.y;
    const int zb   = z >> 4, zh = z & 15;

    // prologue: per-row inverse sums (64 partials per row)
    {
        const int r = tid >> 1;
        const float* pp = partial + ((size_t)z * S_ + bm + r) * 64 + (tid & 1) * 32;
        float s = 0.f;
#pragma unroll
        for (int f = 0; f < 8; f++) {
            float4 u = ((const float4*)pp)[f];
            s += (u.x + u.y) + (u.z + u.w);
        }
        s += __shfl_xor_sync(0xffffffffu, s, 1);
        if (!(tid & 1)) s_inv[r] = 1.f / s;
    }
    __syncthreads();

    const int prow = tid >> 1;
    const int pk   = (tid & 1) * 8;
    const int kkb  = (tid & 1) * 4;
    const __half* P = Pexp + (size_t)z * S_ * S_ + (size_t)(bm + prow) * S_ + pk;
    float* Aout = attn + (size_t)z * S_ * S_ + (size_t)(bm + prow) * S_ + pk;
    const float inv = s_inv[prow];

    // V loader: warp u loads V rows 2u,2u+1 (fp16); lane covers n = 2*lane..2*lane+1
    const int vu = wid;
    const int vn = lane * 2;
    const __half* Vbase = Vg + (size_t)zb * S_ * D_ + (size_t)zh * DK_ + vn;

    float acc[2][4][4];
#pragma unroll
    for (int i = 0; i < 2; i++)
#pragma unroll
        for (int j = 0; j < 4; j++)
#pragma unroll
            for (int e = 0; e < 4; e++) acc[i][j][e] = 0.f;

    uint4 ph;
    __half2 ve, vo;
    // tile 0
    ph = *(const uint4*)(P);
    {
        // write normalized attn (fp32) for these 8 cols
        __half2 h0 = *(__half2*)&ph.x, h1 = *(__half2*)&ph.y;
        __half2 h2 = *(__half2*)&ph.z, h3 = *(__half2*)&ph.w;
        float4 o0, o1;
        o0.x = __low2float(h0) * inv;  o0.y = __high2float(h0) * inv;
        o0.z = __low2float(h1) * inv;  o0.w = __high2float(h1) * inv;
        o1.x = __low2float(h2) * inv;  o1.y = __high2float(h2) * inv;
        o1.z = __low2float(h3) * inv;  o1.w = __high2float(h3) * inv;
        *(float4*)(Aout)     = o0;
        *(float4*)(Aout + 4) = o1;
    }
    ve = *(const __half2*)(Vbase + (size_t)(2 * vu) * D_);
    vo = *(const __half2*)(Vbase + (size_t)(2 * vu + 1) * D_);
    STS8HU(Ps[0], kkb, prow, ph);
    {
        __half2 w0 = __lows2half2(ve, vo);
        __half2 w1 = __highs2half2(ve, vo);
        Vs[0][vu][vn]     = *(uint32_t*)&w0;
        Vs[0][vu][vn + 1] = *(uint32_t*)&w1;
    }
    __syncthreads();

    const int NIT = S_ / 16;
    const int mg  = wm * 32 + (lane >> 2);
    const int ng  = wn * 32 + (lane >> 2);
    const int kl  = lane & 3;

    for (int it = 0; it < NIT; it++) {
        const int cur = it & 1;
        if (it + 1 < NIT) {
            const int k0 = (it + 1) * 16;
            ph = *(const uint4*)(P + k0);
            __half2 h0 = *(__half2*)&ph.x, h1 = *(__half2*)&ph.y;
            __half2 h2 = *(__half2*)&ph.z, h3 = *(__half2*)&ph.w;
            float4 o0, o1;
            o0.x = __low2float(h0) * inv;  o0.y = __high2float(h0) * inv;
            o0.z = __low2float(h1) * inv;  o0.w = __high2float(h1) * inv;
            o1.x = __low2float(h2) * inv;  o1.y = __high2float(h2) * inv;
            o1.z = __low2float(h3) * inv;  o1.w = __high2float(h3) * inv;
            *(float4*)(Aout + k0)     = o0;
            *(float4*)(Aout + k0 + 4) = o1;
            ve = *(const __half2*)(Vbase + (size_t)(k0 + 2 * vu) * D_);
            vo = *(const __half2*)(Vbase + (size_t)(k0 + 2 * vu + 1) * D_);
        }
        {
            uint32_t af[2][4];
#pragma unroll
            for (int i = 0; i < 2; i++) {
                af[i][0] = Ps[cur][kl    ][mg + i * 16];
                af[i][1] = Ps[cur][kl    ][mg + i * 16 + 8];
                af[i][2] = Ps[cur][kl + 4][mg + i * 16];
                af[i][3] = Ps[cur][kl + 4][mg + i * 16 + 8];
            }
            uint32_t bf[4][2];
#pragma unroll
            for (int j = 0; j < 4; j++) {
                bf[j][0] = Vs[cur][kl    ][ng + j * 8];
                bf[j][1] = Vs[cur][kl + 4][ng + j * 8];
            }
#pragma unroll
            for (int j = 0; j < 4; j++)
#pragma unroll
                for (int i = 0; i < 2; i++)
                    mma_f16(acc[i][j], af[i][0], af[i][1], af[i][2], af[i][3],
                            bf[j][0], bf[j][1]);
        }
        if (it + 1 < NIT) {
            const int nxt = cur ^ 1;
            STS8HU(Ps[nxt], kkb, prow, ph);
            __half2 w0 = __lows2half2(ve, vo);
            __half2 w1 = __highs2half2(ve, vo);
            Vs[nxt][vu][vn]     = *(uint32_t*)&w0;
            Vs[nxt][vu][vn + 1] = *(uint32_t*)&w1;
            __syncthreads();
        }
    }

    __half* Cc = ctx + (size_t)zb * S_ * D_ + (size_t)zh * DK_;
    const int row0 = bm + wm * 32 + (lane >> 2);
    const int col0 = wn * 32 + (lane & 3) * 2;
#pragma unroll
    for (int i = 0; i < 2; i++) {
        const float ilo = s_inv[wm * 32 + (lane >> 2) + i * 16];
        const float ihi = s_inv[wm * 32 + (lane >> 2) + i * 16 + 8];
#pragma unroll
        for (int j = 0; j < 4; j++) {
            const int r = row0 + i * 16;
            const int c = col0 + j * 8;
            *(uint32_t*)&Cc[(size_t)r * D_ + c]       = f2h2(acc[i][j][0] * ilo, acc[i][j][1] * ilo);
            *(uint32_t*)&Cc[(size_t)(r + 8) * D_ + c] = f2h2(acc[i][j][2] * ihi, acc[i][j][3] * ihi);
        }
    }
}

// ---------------- launch ----------------
extern "C" void kernel_launch(void* const* d_in, const int* in_sizes, int n_in,
                              void* d_out, int out_size)
{
    const float* query = (const float*)d_in[0];
    const float* key   = (const float*)d_in[1];
    const float* value = (const float*)d_in[2];
    const float* Wq    = (const float*)d_in[3];
    const float* bq    = (const float*)d_in[4];
    const float* Wk    = (const float*)d_in[5];
    const float* bk    = (const float*)d_in[6];
    const float* Wv    = (const float*)d_in[7];
    const float* bv    = (const float*)d_in[8];
    const float* Wo    = (const float*)d_in[9];
    const float* bo    = (const float*)d_in[10];

    float* out  = (float*)d_out;                          // (B,S,D)
    float* attn = out + (size_t)B_ * S_ * D_;             // (B,H,S,S)

    __half *qh, *kh, *vh, *ctxh, *xq, *xk, *xv, *wq, *wk, *wv, *wo, *ph;
    float *part;
    cudaGetSymbolAddress((void**)&qh,   g_qh);
    cudaGetSymbolAddress((void**)&kh,   g_kh);
    cudaGetSymbolAddress((void**)&vh,   g_vh);
    cudaGetSymbolAddress((void**)&ctxh, g_ctxh);
    cudaGetSymbolAddress((void**)&xq,   g_xq);
    cudaGetSymbolAddress((void**)&xk,   g_xk);
    cudaGetSymbolAddress((void**)&xv,   g_xv);
    cudaGetSymbolAddress((void**)&wq,   g_wq);
    cudaGetSymbolAddress((void**)&wk,   g_wk);
    cudaGetSymbolAddress((void**)&wv,   g_wv);
    cudaGetSymbolAddress((void**)&wo,   g_wo);
    cudaGetSymbolAddress((void**)&ph,   g_ph);
    cudaGetSymbolAddress((void**)&part, g_partial);

    // 0) convert inputs + weights to fp16 once
    to_half7<<<8192, 256>>>(query, key, value, Wq, Wk, Wv, Wo,
                            xq, xk, xv, wq, wk, wv, wo);

    // 1) projections: q/k/v = X @ W^T + b  (fp16 x fp16 -> fp16)
    dim3 pgrid(D_ / 128, (B_ * S_) / 128, 1);
    gemm_h<D_, __half, __half, __half, true, false><<<pgrid, 256>>>(xq, wq, bq, qh,
        D_, D_, D_, 0, 0, 0, 0, 0, 0, 1.f, nullptr);
    gemm_h<D_, __half, __half, __half, true, false><<<pgrid, 256>>>(xk, wk, bk, kh,
        D_, D_, D_, 0, 0, 0, 0, 0, 0, 1.f, nullptr);
    gemm_h<D_, __half, __half, __half, true, false><<<pgrid, 256>>>(xv, wv, bv, vh,
        D_, D_, D_, 0, 0, 0, 0, 0, 0, 1.f, nullptr);

    // 2) QK^T -> exp(scores) fp16 scratch + row partial sums
    dim3 qkgrid(S_ / 128, S_ / 128, B_ * H_);
    gemm_h<DK_, __half, __half, __half, false, true><<<qkgrid, 256>>>(qh, kh, nullptr, ph,
        D_, D_, S_,
        (size_t)S_ * D_, (size_t)DK_,
        (size_t)S_ * D_, (size_t)DK_,
        (size_t)H_ * S_ * S_, (size_t)S_ * S_,
        0.125f, part);

    // 3) normalized attn write + ctx = inv * (expP @ V)
    dim3 pvgrid(S_ / 128, B_ * H_);
    pv_h<<<pvgrid, 256>>>(ph, attn, vh, ctxh, part);

    // 4) output projection (fp16 x fp16 -> fp32)
    gemm_h<D_, __half, __half, float, true, false><<<pgrid, 256>>>(ctxh, wo, bo, out,
        D_, D_, D_, 0, 0, 0, 0, 0, 0, 1.f, nullptr);
}

// round 12
// speedup vs baseline: 1.9755x; 1.0101x over previous
#include <cuda_runtime.h>
#include <cuda_fp16.h>
#include <math.h>
#include <stdint.h>
#include <type_traits>

// Problem constants
#define B_ 2
#define S_ 2048
#define D_ 1024
#define H_ 16
#define DK_ 64

// ---------------- scratch (no cudaMalloc allowed) ----------------
__device__ __half g_qh[(size_t)B_ * S_ * D_];
__device__ __half g_kh[(size_t)B_ * S_ * D_];
__device__ __half g_vh[(size_t)B_ * S_ * D_];
__device__ __half g_ctxh[(size_t)B_ * S_ * D_];
// fp16 copies of inputs / weights
__device__ __half g_xq[(size_t)B_ * S_ * D_];
__device__ __half g_xk[(size_t)B_ * S_ * D_];
__device__ __half g_xv[(size_t)B_ * S_ * D_];
__device__ __half g_wq[(size_t)D_ * D_];
__device__ __half g_wk[(size_t)D_ * D_];
__device__ __half g_wv[(size_t)D_ * D_];
__device__ __half g_wo[(size_t)D_ * D_];
// fp16 exp(scores) scratch
__device__ __half g_ph[(size_t)B_ * H_ * S_ * S_];
// per-row exp partial sums: [z][row][16 bn-tiles * 4 wn] = 64 partials/row
__device__ float g_partial[(size_t)B_ * H_ * S_ * 64];

// ---------------- FP16 helpers ----------------
__device__ __forceinline__ uint32_t f2h2(float lo, float hi) {
    __half2 h = __floats2half2_rn(lo, hi);
    return *(uint32_t*)&h;
}

__device__ __forceinline__ void mma_f16(float c[4],
    uint32_t a0, uint32_t a1, uint32_t a2, uint32_t a3,
    uint32_t b0, uint32_t b1)
{
    asm volatile(
        "mma.sync.aligned.m16n8k16.row.col.f32.f16.f16.f32 "
        "{%0,%1,%2,%3}, {%4,%5,%6,%7}, {%8,%9}, {%0,%1,%2,%3};"
        : "+f"(c[0]), "+f"(c[1]), "+f"(c[2]), "+f"(c[3])
        : "r"(a0), "r"(a1), "r"(a2), "r"(a3), "r"(b0), "r"(b1));
}

#define STS8H(s, kkb, r, v0, v1) do { \
    (s)[(kkb) + 0][r] = f2h2((v0).x, (v0).y); \
    (s)[(kkb) + 1][r] = f2h2((v0).z, (v0).w); \
    (s)[(kkb) + 2][r] = f2h2((v1).x, (v1).y); \
    (s)[(kkb) + 3][r] = f2h2((v1).z, (v1).w); \
} while (0)

#define STS8HU(s, kkb, r, u) do { \
    (s)[(kkb) + 0][r] = (u).x; \
    (s)[(kkb) + 1][r] = (u).y; \
    (s)[(kkb) + 2][r] = (u).z; \
    (s)[(kkb) + 3][r] = (u).w; \
} while (0)

// ================= fp32 -> fp16 conversion (inputs + weights) =================
__global__ __launch_bounds__(256) void to_half7(
    const float* __restrict__ s0, const float* __restrict__ s1, const float* __restrict__ s2,
    const float* __restrict__ s3, const float* __restrict__ s4, const float* __restrict__ s5,
    const float* __restrict__ s6,
    __half* __restrict__ d0, __half* __restrict__ d1, __half* __restrict__ d2,
    __half* __restrict__ d3, __half* __restrict__ d4, __half* __restrict__ d5,
    __half* __restrict__ d6)
{
    int b = blockIdx.x;
    const float* src; __half* dst; int off;
    if      (b < 2048) { src = s0; dst = d0; off = b; }
    else if (b < 4096) { src = s1; dst = d1; off = b - 2048; }
    else if (b < 6144) { src = s2; dst = d2; off = b - 4096; }
    else {
        int w = (b - 6144) >> 9;
        off = (b - 6144) & 511;
        src = (w == 0) ? s3 : (w == 1) ? s4 : (w == 2) ? s5 : s6;
        dst = (w == 0) ? d3 : (w == 1) ? d4 : (w == 2) ? d5 : d6;
    }
    size_t base = (size_t)off * 2048 + threadIdx.x * 8;
    float4 u0 = *(const float4*)(src + base);
    float4 u1 = *(const float4*)(src + base + 4);
    uint4 o;
    o.x = f2h2(u0.x, u0.y); o.y = f2h2(u0.z, u0.w);
    o.z = f2h2(u1.x, u1.y); o.w = f2h2(u1.z, u1.w);
    *(uint4*)(dst + base) = o;
}

// ============ core fp16 NT GEMM mainloop (shared by all GEMM kernels) ========
// A[128, KDIM] rows at Ap (fp16), B[128, KDIM] rows at Bp (fp16), both k-major.
// Returns 4x4x4 fp32 accum for the calling warp's 64x32 tile.
template<int KDIM>
__device__ __forceinline__ void gemm_core(
    const __half* __restrict__ Ap, const __half* __restrict__ Bp,
    uint32_t (*As)[8][136], uint32_t (*Bs)[8][136],
    int tid, int lane, int wm, int wn,
    float acc[4][4][4])
{
    const int arow = tid >> 1;
    const int kkb  = (tid & 1) * 4;

    uint4 ahv = *(const uint4*)(Ap);
    uint4 bhv = *(const uint4*)(Bp);
    STS8HU(As[0], kkb, arow, ahv);
    STS8HU(Bs[0], kkb, arow, bhv);
    __syncthreads();

    const int NIT = KDIM / 16;
    const int mg  = wm * 64 + (lane >> 2);
    const int ng  = wn * 32 + (lane >> 2);
    const int kl  = lane & 3;

    for (int it = 0; it < NIT; it++) {
        const int cur = it & 1;
        if (it + 1 < NIT) {
            const int k0 = (it + 1) * 16;
            ahv = *(const uint4*)(Ap + k0);
            bhv = *(const uint4*)(Bp + k0);
        }
        {
            uint32_t af[4][4];
#pragma unroll
            for (int i = 0; i < 4; i++) {
                af[i][0] = As[cur][kl    ][mg + i * 16];
                af[i][1] = As[cur][kl    ][mg + i * 16 + 8];
                af[i][2] = As[cur][kl + 4][mg + i * 16];
                af[i][3] = As[cur][kl + 4][mg + i * 16 + 8];
            }
            uint32_t bf[4][2];
#pragma unroll
            for (int j = 0; j < 4; j++) {
                bf[j][0] = Bs[cur][kl    ][ng + j * 8];
                bf[j][1] = Bs[cur][kl + 4][ng + j * 8];
            }
#pragma unroll
            for (int j = 0; j < 4; j++)
#pragma unroll
                for (int i = 0; i < 4; i++)
                    mma_f16(acc[i][j], af[i][0], af[i][1], af[i][2], af[i][3],
                            bf[j][0], bf[j][1]);
        }
        if (it + 1 < NIT) {
            const int nxt = cur ^ 1;
            STS8HU(As[nxt], kkb, arow, ahv);
            STS8HU(Bs[nxt], kkb, arow, bhv);
            __syncthreads();
        }
    }
}

// ================= fused q/k/v projections =================
// grid.z selects (X, W, bias, C) triple. Block 128x128, 256 threads.
template<class TC>
__global__ __launch_bounds__(256, 2) void proj3_h(
    const __half* __restrict__ X0, const __half* __restrict__ X1, const __half* __restrict__ X2,
    const __half* __restrict__ W0, const __half* __restrict__ W1, const __half* __restrict__ W2,
    const float* __restrict__ bi0, const float* __restrict__ bi1, const float* __restrict__ bi2,
    TC* __restrict__ C0, TC* __restrict__ C1, TC* __restrict__ C2)
{
    constexpr bool OUT_HALF = std::is_same<TC, __half>::value;
    __shared__ uint32_t As[2][8][136];
    __shared__ uint32_t Bs[2][8][136];

    const int tid  = threadIdx.x;
    const int lane = tid & 31;
    const int wid  = tid >> 5;
    const int wm   = wid & 1;
    const int wn   = wid >> 1;
    const int bm   = blockIdx.y * 128;
    const int bn   = blockIdx.x * 128;
    const int z    = blockIdx.z;

    const __half* X    = (z == 0) ? X0 : (z == 1) ? X1 : X2;
    const __half* W    = (z == 0) ? W0 : (z == 1) ? W1 : W2;
    const float*  bias = (z == 0) ? bi0 : (z == 1) ? bi1 : bi2;
    TC*           C    = (z == 0) ? C0 : (z == 1) ? C1 : C2;

    const int arow = tid >> 1;
    const int ak   = (tid & 1) * 8;
    const __half* Ap = X + (size_t)(bm + arow) * D_ + ak;
    const __half* Bp = W + (size_t)(bn + arow) * D_ + ak;

    float acc[4][4][4];
#pragma unroll
    for (int i = 0; i < 4; i++)
#pragma unroll
        for (int j = 0; j < 4; j++)
#pragma unroll
            for (int e = 0; e < 4; e++) acc[i][j][e] = 0.f;

    gemm_core<D_>(Ap, Bp, As, Bs, tid, lane, wm, wn, acc);

    const int rl   = wm * 64 + (lane >> 2);
    const int col0 = bn + wn * 32 + (lane & 3) * 2;
    float2 bvj[4];
#pragma unroll
    for (int j = 0; j < 4; j++)
        bvj[j] = *(const float2*)&bias[col0 + j * 8];

#pragma unroll
    for (int i = 0; i < 4; i++) {
#pragma unroll
        for (int j = 0; j < 4; j++) {
            const int r = bm + rl + i * 16;
            const int c = col0 + j * 8;
            float lx = acc[i][j][0] + bvj[j].x, ly = acc[i][j][1] + bvj[j].y;
            float hx = acc[i][j][2] + bvj[j].x, hy = acc[i][j][3] + bvj[j].y;
            if constexpr (OUT_HALF) {
                *(uint32_t*)&C[(size_t)r * D_ + c]       = f2h2(lx, ly);
                *(uint32_t*)&C[(size_t)(r + 8) * D_ + c] = f2h2(hx, hy);
            } else {
                float2 lo; lo.x = lx; lo.y = ly;
                float2 hi; hi.x = hx; hi.y = hy;
                *(float2*)&C[(size_t)r * D_ + c]       = lo;
                *(float2*)&C[(size_t)(r + 8) * D_ + c] = hi;
            }
        }
    }
}

// ================= QK^T -> exp fp16 scratch + partials =================
__global__ __launch_bounds__(256, 2) void qk_h(
    const __half* __restrict__ Q, const __half* __restrict__ K,
    __half* __restrict__ Pexp, float* __restrict__ partial)
{
    __shared__ uint32_t As[2][8][136];
    __shared__ uint32_t Bs[2][8][136];

    const int tid  = threadIdx.x;
    const int lane = tid & 31;
    const int wid  = tid >> 5;
    const int wm   = wid & 1;
    const int wn   = wid >> 1;
    const int bm   = blockIdx.y * 128;
    const int bn   = blockIdx.x * 128;
    const int z    = blockIdx.z;
    const int zb   = z >> 4, zh = z & 15;
    const size_t base = (size_t)zb * S_ * D_ + (size_t)zh * DK_;

    const int arow = tid >> 1;
    const int ak   = (tid & 1) * 8;
    const __half* Ap = Q + base + (size_t)(bm + arow) * D_ + ak;
    const __half* Bp = K + base + (size_t)(bn + arow) * D_ + ak;

    float acc[4][4][4];
#pragma unroll
    for (int i = 0; i < 4; i++)
#pragma unroll
        for (int j = 0; j < 4; j++)
#pragma unroll
            for (int e = 0; e < 4; e++) acc[i][j][e] = 0.f;

    gemm_core<DK_>(Ap, Bp, As, Bs, tid, lane, wm, wn, acc);

    __half* Cp = Pexp + (size_t)z * S_ * S_;
    const int rl   = wm * 64 + (lane >> 2);
    const int col0 = bn + wn * 32 + (lane & 3) * 2;

#pragma unroll
    for (int i = 0; i < 4; i++) {
        const int rlo = bm + rl + i * 16;
        const int rhi = rlo + 8;
        float pl = 0.f, ph = 0.f;
#pragma unroll
        for (int j = 0; j < 4; j++) {
            float e0 = __expf(acc[i][j][0] * 0.125f);
            float e1 = __expf(acc[i][j][1] * 0.125f);
            float e2 = __expf(acc[i][j][2] * 0.125f);
            float e3 = __expf(acc[i][j][3] * 0.125f);
            *(uint32_t*)&Cp[(size_t)rlo * S_ + col0 + j * 8] = f2h2(e0, e1);
            *(uint32_t*)&Cp[(size_t)rhi * S_ + col0 + j * 8] = f2h2(e2, e3);
            pl += e0 + e1;
            ph += e2 + e3;
        }
        pl += __shfl_xor_sync(0xffffffffu, pl, 1);
        pl += __shfl_xor_sync(0xffffffffu, pl, 2);
        ph += __shfl_xor_sync(0xffffffffu, ph, 1);
        ph += __shfl_xor_sync(0xffffffffu, ph, 2);
        if ((lane & 3) == 0) {
            partial[((size_t)z * S_ + rlo) * 64 + blockIdx.x * 4 + wn] = pl;
            partial[((size_t)z * S_ + rhi) * 64 + blockIdx.x * 4 + wn] = ph;
        }
    }
}

// ================= PV: write normalized attn (fp32) + ctx = inv * (expP @ V) ===
__global__ __launch_bounds__(256, 2) void pv_h(
    const __half* __restrict__ Pexp, float* __restrict__ attn,
    const __half* __restrict__ Vg,
    __half* __restrict__ ctx, const float* __restrict__ partial)
{
    __shared__ uint32_t Ps[2][8][136];
    __shared__ uint32_t Vs[2][8][72];
    __shared__ float s_inv[128];

    const int tid  = threadIdx.x;
    const int lane = tid & 31;
    const int wid  = tid >> 5;
    const int wm   = wid & 3;
    const int wn   = wid >> 2;
    const int bm   = blockIdx.x * 128;
    const int z    = blockIdx.y;
    const int zb   = z >> 4, zh = z & 15;

    // prologue: per-row inverse sums (64 partials per row)
    {
        const int r = tid >> 1;
        const float* pp = partial + ((size_t)z * S_ + bm + r) * 64 + (tid & 1) * 32;
        float s = 0.f;
#pragma unroll
        for (int f = 0; f < 8; f++) {
            float4 u = ((const float4*)pp)[f];
            s += (u.x + u.y) + (u.z + u.w);
        }
        s += __shfl_xor_sync(0xffffffffu, s, 1);
        if (!(tid & 1)) s_inv[r] = 1.f / s;
    }
    __syncthreads();

    const int prow = tid >> 1;
    const int pk   = (tid & 1) * 8;
    const int kkb  = (tid & 1) * 4;
    const __half* P = Pexp + (size_t)z * S_ * S_ + (size_t)(bm + prow) * S_ + pk;
    float* Aout = attn + (size_t)z * S_ * S_ + (size_t)(bm + prow) * S_ + pk;
    const float inv = s_inv[prow];

    const int vu = wid;
    const int vn = lane * 2;
    const __half* Vbase = Vg + (size_t)zb * S_ * D_ + (size_t)zh * DK_ + vn;

    float acc[2][4][4];
#pragma unroll
    for (int i = 0; i < 2; i++)
#pragma unroll
        for (int j = 0; j < 4; j++)
#pragma unroll
            for (int e = 0; e < 4; e++) acc[i][j][e] = 0.f;

    uint4 ph;
    __half2 ve, vo;
    ph = *(const uint4*)(P);
    {
        __half2 h0 = *(__half2*)&ph.x, h1 = *(__half2*)&ph.y;
        __half2 h2 = *(__half2*)&ph.z, h3 = *(__half2*)&ph.w;
        float4 o0, o1;
        o0.x = __low2float(h0) * inv;  o0.y = __high2float(h0) * inv;
        o0.z = __low2float(h1) * inv;  o0.w = __high2float(h1) * inv;
        o1.x = __low2float(h2) * inv;  o1.y = __high2float(h2) * inv;
        o1.z = __low2float(h3) * inv;  o1.w = __high2float(h3) * inv;
        *(float4*)(Aout)     = o0;
        *(float4*)(Aout + 4) = o1;
    }
    ve = *(const __half2*)(Vbase + (size_t)(2 * vu) * D_);
    vo = *(const __half2*)(Vbase + (size_t)(2 * vu + 1) * D_);
    STS8HU(Ps[0], kkb, prow, ph);
    {
        __half2 w0 = __lows2half2(ve, vo);
        __half2 w1 = __highs2half2(ve, vo);
        Vs[0][vu][vn]     = *(uint32_t*)&w0;
        Vs[0][vu][vn + 1] = *(uint32_t*)&w1;
    }
    __syncthreads();

    const int NIT = S_ / 16;
    const int mg  = wm * 32 + (lane >> 2);
    const int ng  = wn * 32 + (lane >> 2);
    const int kl  = lane & 3;

    for (int it = 0; it < NIT; it++) {
        const int cur = it & 1;
        if (it + 1 < NIT) {
            const int k0 = (it + 1) * 16;
            ph = *(const uint4*)(P + k0);
            __half2 h0 = *(__half2*)&ph.x, h1 = *(__half2*)&ph.y;
            __half2 h2 = *(__half2*)&ph.z, h3 = *(__half2*)&ph.w;
            float4 o0, o1;
            o0.x = __low2float(h0) * inv;  o0.y = __high2float(h0) * inv;
            o0.z = __low2float(h1) * inv;  o0.w = __high2float(h1) * inv;
            o1.x = __low2float(h2) * inv;  o1.y = __high2float(h2) * inv;
            o1.z = __low2float(h3) * inv;  o1.w = __high2float(h3) * inv;
            *(float4*)(Aout + k0)     = o0;
            *(float4*)(Aout + k0 + 4) = o1;
            ve = *(const __half2*)(Vbase + (size_t)(k0 + 2 * vu) * D_);
            vo = *(const __half2*)(Vbase + (size_t)(k0 + 2 * vu + 1) * D_);
        }
        {
            uint32_t af[2][4];
#pragma unroll
            for (int i = 0; i < 2; i++) {
                af[i][0] = Ps[cur][kl    ][mg + i * 16];
                af[i][1] = Ps[cur][kl    ][mg + i * 16 + 8];
                af[i][2] = Ps[cur][kl + 4][mg + i * 16];
                af[i][3] = Ps[cur][kl + 4][mg + i * 16 + 8];
            }
            uint32_t bf[4][2];
#pragma unroll
            for (int j = 0; j < 4; j++) {
                bf[j][0] = Vs[cur][kl    ][ng + j * 8];
                bf[j][1] = Vs[cur][kl + 4][ng + j * 8];
            }
#pragma unroll
            for (int j = 0; j < 4; j++)
#pragma unroll
                for (int i = 0; i < 2; i++)
                    mma_f16(acc[i][j], af[i][0], af[i][1], af[i][2], af[i][3],
                            bf[j][0], bf[j][1]);
        }
        if (it + 1 < NIT) {
            const int nxt = cur ^ 1;
            STS8HU(Ps[nxt], kkb, prow, ph);
            __half2 w0 = __lows2half2(ve, vo);
            __half2 w1 = __highs2half2(ve, vo);
            Vs[nxt][vu][vn]     = *(uint32_t*)&w0;
            Vs[nxt][vu][vn + 1] = *(uint32_t*)&w1;
            __syncthreads();
        }
    }

    __half* Cc = ctx + (size_t)zb * S_ * D_ + (size_t)zh * DK_;
    const int row0 = bm + wm * 32 + (lane >> 2);
    const int col0 = wn * 32 + (lane & 3) * 2;
#pragma unroll
    for (int i = 0; i < 2; i++) {
        const float ilo = s_inv[wm * 32 + (lane >> 2) + i * 16];
        const float ihi = s_inv[wm * 32 + (lane >> 2) + i * 16 + 8];
#pragma unroll
        for (int j = 0; j < 4; j++) {
            const int r = row0 + i * 16;
            const int c = col0 + j * 8;
            *(uint32_t*)&Cc[(size_t)r * D_ + c]       = f2h2(acc[i][j][0] * ilo, acc[i][j][1] * ilo);
            *(uint32_t*)&Cc[(size_t)(r + 8) * D_ + c] = f2h2(acc[i][j][2] * ihi, acc[i][j][3] * ihi);
        }
    }
}

// ---------------- launch ----------------
extern "C" void kernel_launch(void* const* d_in, const int* in_sizes, int n_in,
                              void* d_out, int out_size)
{
    const float* query = (const float*)d_in[0];
    const float* key   = (const float*)d_in[1];
    const float* value = (const float*)d_in[2];
    const float* Wq    = (const float*)d_in[3];
    const float* bq    = (const float*)d_in[4];
    const float* Wk    = (const float*)d_in[5];
    const float* bk    = (const float*)d_in[6];
    const float* Wv    = (const float*)d_in[7];
    const float* bv    = (const float*)d_in[8];
    const float* Wo    = (const float*)d_in[9];
    const float* bo    = (const float*)d_in[10];

    float* out  = (float*)d_out;                          // (B,S,D)
    float* attn = out + (size_t)B_ * S_ * D_;             // (B,H,S,S)

    __half *qh, *kh, *vh, *ctxh, *xq, *xk, *xv, *wq, *wk, *wv, *wo, *ph;
    float *part;
    cudaGetSymbolAddress((void**)&qh,   g_qh);
    cudaGetSymbolAddress((void**)&kh,   g_kh);
    cudaGetSymbolAddress((void**)&vh,   g_vh);
    cudaGetSymbolAddress((void**)&ctxh, g_ctxh);
    cudaGetSymbolAddress((void**)&xq,   g_xq);
    cudaGetSymbolAddress((void**)&xk,   g_xk);
    cudaGetSymbolAddress((void**)&xv,   g_xv);
    cudaGetSymbolAddress((void**)&wq,   g_wq);
    cudaGetSymbolAddress((void**)&wk,   g_wk);
    cudaGetSymbolAddress((void**)&wv,   g_wv);
    cudaGetSymbolAddress((void**)&wo,   g_wo);
    cudaGetSymbolAddress((void**)&ph,   g_ph);
    cudaGetSymbolAddress((void**)&part, g_partial);

    // 0) convert inputs + weights to fp16 once
    to_half7<<<8192, 256>>>(query, key, value, Wq, Wk, Wv, Wo,
                            xq, xk, xv, wq, wk, wv, wo);

    // 1) fused q/k/v projections (grid.z = 3)
    dim3 pgrid(D_ / 128, (B_ * S_) / 128, 3);
    proj3_h<__half><<<pgrid, 256>>>(xq, xk, xv, wq, wk, wv, bq, bk, bv, qh, kh, vh);

    // 2) QK^T -> exp fp16 scratch + partials
    dim3 qkgrid(S_ / 128, S_ / 128, B_ * H_);
    qk_h<<<qkgrid, 256>>>(qh, kh, ph, part);

    // 3) normalized attn write + ctx = inv * (expP @ V)
    dim3 pvgrid(S_ / 128, B_ * H_);
    pv_h<<<pvgrid, 256>>>(ph, attn, vh, ctxh, part);

    // 4) output projection (fp16 x fp16 -> fp32)
    dim3 ogrid(D_ / 128, (B_ * S_) / 128, 1);
    proj3_h<float><<<ogrid, 256>>>(ctxh, ctxh, ctxh, wo, wo, wo, bo, bo, bo, out, out, out);
}

// round 13
// speedup vs baseline: 2.3163x; 1.1725x over previous
#include <cuda_runtime.h>
#include <cuda_fp16.h>
#include <math.h>
#include <stdint.h>
#include <type_traits>

// Problem constants
#define B_ 2
#define S_ 2048
#define D_ 1024
#define H_ 16
#define DK_ 64

// ---------------- scratch (no cudaMalloc allowed) ----------------
__device__ __half g_qh[(size_t)B_ * S_ * D_];
__device__ __half g_kh[(size_t)B_ * S_ * D_];
__device__ __half g_vh[(size_t)B_ * S_ * D_];
__device__ __half g_ctxh[(size_t)B_ * S_ * D_];
// fp16 copies of inputs / weights
__device__ __half g_xq[(size_t)B_ * S_ * D_];
__device__ __half g_xk[(size_t)B_ * S_ * D_];
__device__ __half g_xv[(size_t)B_ * S_ * D_];
__device__ __half g_wq[(size_t)D_ * D_];
__device__ __half g_wk[(size_t)D_ * D_];
__device__ __half g_wv[(size_t)D_ * D_];
__device__ __half g_wo[(size_t)D_ * D_];
// fp16 exp(scores) scratch
__device__ __half g_ph[(size_t)B_ * H_ * S_ * S_];
// per-row exp partial sums: [z][row][16 bn-tiles * 4 wn] = 64 partials/row
__device__ float g_partial[(size_t)B_ * H_ * S_ * 64];

// ---------------- FP16 helpers ----------------
__device__ __forceinline__ uint32_t f2h2(float lo, float hi) {
    __half2 h = __floats2half2_rn(lo, hi);
    return *(uint32_t*)&h;
}

__device__ __forceinline__ void mma_f16(float c[4],
    uint32_t a0, uint32_t a1, uint32_t a2, uint32_t a3,
    uint32_t b0, uint32_t b1)
{
    asm volatile(
        "mma.sync.aligned.m16n8k16.row.col.f32.f16.f16.f32 "
        "{%0,%1,%2,%3}, {%4,%5,%6,%7}, {%8,%9}, {%0,%1,%2,%3};"
        : "+f"(c[0]), "+f"(c[1]), "+f"(c[2]), "+f"(c[3])
        : "r"(a0), "r"(a1), "r"(a2), "r"(a3), "r"(b0), "r"(b1));
}

#define STS8HU(s, kkb, r, u) do { \
    (s)[(kkb) + 0][r] = (u).x; \
    (s)[(kkb) + 1][r] = (u).y; \
    (s)[(kkb) + 2][r] = (u).z; \
    (s)[(kkb) + 3][r] = (u).w; \
} while (0)

// ---------------- cp.async helpers ----------------
#define CP_ASYNC16(saddr, gptr) \
    asm volatile("cp.async.cg.shared.global [%0], [%1], 16;" \
                 :: "r"(saddr), "l"(gptr) : "memory")
#define CP_COMMIT() asm volatile("cp.async.commit_group;" ::: "memory")
#define CP_WAIT1()  asm volatile("cp.async.wait_group 1;" ::: "memory")

// ================= fp32 -> fp16 conversion (inputs + weights) =================
__global__ __launch_bounds__(256) void to_half7(
    const float* __restrict__ s0, const float* __restrict__ s1, const float* __restrict__ s2,
    const float* __restrict__ s3, const float* __restrict__ s4, const float* __restrict__ s5,
    const float* __restrict__ s6,
    __half* __restrict__ d0, __half* __restrict__ d1, __half* __restrict__ d2,
    __half* __restrict__ d3, __half* __restrict__ d4, __half* __restrict__ d5,
    __half* __restrict__ d6)
{
    int b = blockIdx.x;
    const float* src; __half* dst; int off;
    if      (b < 2048) { src = s0; dst = d0; off = b; }
    else if (b < 4096) { src = s1; dst = d1; off = b - 2048; }
    else if (b < 6144) { src = s2; dst = d2; off = b - 4096; }
    else {
        int w = (b - 6144) >> 9;
        off = (b - 6144) & 511;
        src = (w == 0) ? s3 : (w == 1) ? s4 : (w == 2) ? s5 : s6;
        dst = (w == 0) ? d3 : (w == 1) ? d4 : (w == 2) ? d5 : d6;
    }
    size_t base = (size_t)off * 2048 + threadIdx.x * 8;
    float4 u0 = *(const float4*)(src + base);
    float4 u1 = *(const float4*)(src + base + 4);
    uint4 o;
    o.x = f2h2(u0.x, u0.y); o.y = f2h2(u0.z, u0.w);
    o.z = f2h2(u1.x, u1.y); o.w = f2h2(u1.z, u1.w);
    *(uint4*)(dst + base) = o;
}

// ============ core fp16 NT GEMM mainloop — cp.async 3-stage ============
// smem layout per stage: [128 rows][12 words] (word = 2 fp16 along k, 8 used + pad 4).
// Fragment LDS (12*row + kp) % 32 covers all banks -> conflict-free.
template<int KDIM>
__device__ __forceinline__ void gemm_core_cp(
    const __half* __restrict__ Ag, const __half* __restrict__ Bg,  // per-thread: row*ld + ak
    uint32_t* __restrict__ As, uint32_t* __restrict__ Bs,          // 3*128*12 words each
    int tid, int lane, int wm, int wn, float acc[4][4][4])
{
    const int arow = tid >> 1;
    const int kk4  = (tid & 1) * 4;
    const uint32_t a_sm = (uint32_t)__cvta_generic_to_shared(As) + (uint32_t)(arow * 48 + kk4 * 4);
    const uint32_t b_sm = (uint32_t)__cvta_generic_to_shared(Bs) + (uint32_t)(arow * 48 + kk4 * 4);
    const int NIT = KDIM / 16;

    // prologue: stages 0,1
#pragma unroll
    for (int s = 0; s < 2; s++) {
        if (s < NIT) {
            CP_ASYNC16(a_sm + s * (128 * 48), Ag + s * 16);
            CP_ASYNC16(b_sm + s * (128 * 48), Bg + s * 16);
        }
        CP_COMMIT();
    }

    const int mg = wm * 64 + (lane >> 2);
    const int ng = wn * 32 + (lane >> 2);
    const int kl = lane & 3;

    int stage = 0;
    for (int it = 0; it < NIT; it++) {
        CP_WAIT1();
        __syncthreads();
        // issue stage it+2 (slot freed by compute(it-1), guaranteed by the sync above)
        {
            int s2 = stage + 2; if (s2 >= 3) s2 -= 3;
            if (it + 2 < NIT) {
                CP_ASYNC16(a_sm + s2 * (128 * 48), Ag + (it + 2) * 16);
                CP_ASYNC16(b_sm + s2 * (128 * 48), Bg + (it + 2) * 16);
            }
            CP_COMMIT();
        }
        // compute on current stage
        const uint32_t* Asb = As + stage * (128 * 12);
        const uint32_t* Bsb = Bs + stage * (128 * 12);
        uint32_t af[4][4];
#pragma unroll
        for (int i = 0; i < 4; i++) {
            af[i][0] = Asb[(mg + i * 16) * 12 + kl];
            af[i][1] = Asb[(mg + i * 16 + 8) * 12 + kl];
            af[i][2] = Asb[(mg + i * 16) * 12 + kl + 4];
            af[i][3] = Asb[(mg + i * 16 + 8) * 12 + kl + 4];
        }
        uint32_t bf[4][2];
#pragma unroll
        for (int j = 0; j < 4; j++) {
            bf[j][0] = Bsb[(ng + j * 8) * 12 + kl];
            bf[j][1] = Bsb[(ng + j * 8) * 12 + kl + 4];
        }
#pragma unroll
        for (int j = 0; j < 4; j++)
#pragma unroll
            for (int i = 0; i < 4; i++)
                mma_f16(acc[i][j], af[i][0], af[i][1], af[i][2], af[i][3],
                        bf[j][0], bf[j][1]);

        stage++; if (stage == 3) stage = 0;
    }
}

// ================= fused q/k/v projections =================
template<class TC>
__global__ __launch_bounds__(256, 2) void proj3_h(
    const __half* __restrict__ X0, const __half* __restrict__ X1, const __half* __restrict__ X2,
    const __half* __restrict__ W0, const __half* __restrict__ W1, const __half* __restrict__ W2,
    const float* __restrict__ bi0, const float* __restrict__ bi1, const float* __restrict__ bi2,
    TC* __restrict__ C0, TC* __restrict__ C1, TC* __restrict__ C2)
{
    constexpr bool OUT_HALF = std::is_same<TC, __half>::value;
    __shared__ __align__(16) uint32_t As[3 * 128 * 12];
    __shared__ __align__(16) uint32_t Bs[3 * 128 * 12];

    const int tid  = threadIdx.x;
    const int lane = tid & 31;
    const int wid  = tid >> 5;
    const int wm   = wid & 1;
    const int wn   = wid >> 1;
    const int bm   = blockIdx.y * 128;
    const int bn   = blockIdx.x * 128;
    const int z    = blockIdx.z;

    const __half* X    = (z == 0) ? X0 : (z == 1) ? X1 : X2;
    const __half* W    = (z == 0) ? W0 : (z == 1) ? W1 : W2;
    const float*  bias = (z == 0) ? bi0 : (z == 1) ? bi1 : bi2;
    TC*           C    = (z == 0) ? C0 : (z == 1) ? C1 : C2;

    const int arow = tid >> 1;
    const int ak   = (tid & 1) * 8;
    const __half* Ap = X + (size_t)(bm + arow) * D_ + ak;
    const __half* Bp = W + (size_t)(bn + arow) * D_ + ak;

    float acc[4][4][4];
#pragma unroll
    for (int i = 0; i < 4; i++)
#pragma unroll
        for (int j = 0; j < 4; j++)
#pragma unroll
            for (int e = 0; e < 4; e++) acc[i][j][e] = 0.f;

    gemm_core_cp<D_>(Ap, Bp, As, Bs, tid, lane, wm, wn, acc);

    const int rl   = wm * 64 + (lane >> 2);
    const int col0 = bn + wn * 32 + (lane & 3) * 2;
    float2 bvj[4];
#pragma unroll
    for (int j = 0; j < 4; j++)
        bvj[j] = *(const float2*)&bias[col0 + j * 8];

#pragma unroll
    for (int i = 0; i < 4; i++) {
#pragma unroll
        for (int j = 0; j < 4; j++) {
            const int r = bm + rl + i * 16;
            const int c = col0 + j * 8;
            float lx = acc[i][j][0] + bvj[j].x, ly = acc[i][j][1] + bvj[j].y;
            float hx = acc[i][j][2] + bvj[j].x, hy = acc[i][j][3] + bvj[j].y;
            if constexpr (OUT_HALF) {
                *(uint32_t*)&C[(size_t)r * D_ + c]       = f2h2(lx, ly);
                *(uint32_t*)&C[(size_t)(r + 8) * D_ + c] = f2h2(hx, hy);
            } else {
                float2 lo; lo.x = lx; lo.y = ly;
                float2 hi; hi.x = hx; hi.y = hy;
                *(float2*)&C[(size_t)r * D_ + c]       = lo;
                *(float2*)&C[(size_t)(r + 8) * D_ + c] = hi;
            }
        }
    }
}

// ================= QK^T -> exp fp16 scratch + partials =================
__global__ __launch_bounds__(256, 2) void qk_h(
    const __half* __restrict__ Q, const __half* __restrict__ K,
    __half* __restrict__ Pexp, float* __restrict__ partial)
{
    __shared__ __align__(16) uint32_t As[3 * 128 * 12];
    __shared__ __align__(16) uint32_t Bs[3 * 128 * 12];

    const int tid  = threadIdx.x;
    const int lane = tid & 31;
    const int wid  = tid >> 5;
    const int wm   = wid & 1;
    const int wn   = wid >> 1;
    const int bm   = blockIdx.y * 128;
    const int bn   = blockIdx.x * 128;
    const int z    = blockIdx.z;
    const int zb   = z >> 4, zh = z & 15;
    const size_t base = (size_t)zb * S_ * D_ + (size_t)zh * DK_;

    const int arow = tid >> 1;
    const int ak   = (tid & 1) * 8;
    const __half* Ap = Q + base + (size_t)(bm + arow) * D_ + ak;
    const __half* Bp = K + base + (size_t)(bn + arow) * D_ + ak;

    float acc[4][4][4];
#pragma unroll
    for (int i = 0; i < 4; i++)
#pragma unroll
        for (int j = 0; j < 4; j++)
#pragma unroll
            for (int e = 0; e < 4; e++) acc[i][j][e] = 0.f;

    gemm_core_cp<DK_>(Ap, Bp, As, Bs, tid, lane, wm, wn, acc);

    __half* Cp = Pexp + (size_t)z * S_ * S_;
    const int rl   = wm * 64 + (lane >> 2);
    const int col0 = bn + wn * 32 + (lane & 3) * 2;

#pragma unroll
    for (int i = 0; i < 4; i++) {
        const int rlo = bm + rl + i * 16;
        const int rhi = rlo + 8;
        float pl = 0.f, ph = 0.f;
#pragma unroll
        for (int j = 0; j < 4; j++) {
            float e0 = __expf(acc[i][j][0] * 0.125f);
            float e1 = __expf(acc[i][j][1] * 0.125f);
            float e2 = __expf(acc[i][j][2] * 0.125f);
            float e3 = __expf(acc[i][j][3] * 0.125f);
            *(uint32_t*)&Cp[(size_t)rlo * S_ + col0 + j * 8] = f2h2(e0, e1);
            *(uint32_t*)&Cp[(size_t)rhi * S_ + col0 + j * 8] = f2h2(e2, e3);
            pl += e0 + e1;
            ph += e2 + e3;
        }
        pl += __shfl_xor_sync(0xffffffffu, pl, 1);
        pl += __shfl_xor_sync(0xffffffffu, pl, 2);
        ph += __shfl_xor_sync(0xffffffffu, ph, 1);
        ph += __shfl_xor_sync(0xffffffffu, ph, 2);
        if ((lane & 3) == 0) {
            partial[((size_t)z * S_ + rlo) * 64 + blockIdx.x * 4 + wn] = pl;
            partial[((size_t)z * S_ + rhi) * 64 + blockIdx.x * 4 + wn] = ph;
        }
    }
}

// ================= PV: depth-2 register prefetch =================
__global__ __launch_bounds__(256, 2) void pv_h(
    const __half* __restrict__ Pexp, float* __restrict__ attn,
    const __half* __restrict__ Vg,
    __half* __restrict__ ctx, const float* __restrict__ partial)
{
    __shared__ uint32_t Ps[2][8][136];
    __shared__ uint32_t Vs[2][8][72];
    __shared__ float s_inv[128];

    const int tid  = threadIdx.x;
    const int lane = tid & 31;
    const int wid  = tid >> 5;
    const int wm   = wid & 3;
    const int wn   = wid >> 2;
    const int bm   = blockIdx.x * 128;
    const int z    = blockIdx.y;
    const int zb   = z >> 4, zh = z & 15;

    // prologue: per-row inverse sums (64 partials per row)
    {
        const int r = tid >> 1;
        const float* pp = partial + ((size_t)z * S_ + bm + r) * 64 + (tid & 1) * 32;
        float s = 0.f;
#pragma unroll
        for (int f = 0; f < 8; f++) {
            float4 u = ((const float4*)pp)[f];
            s += (u.x + u.y) + (u.z + u.w);
        }
        s += __shfl_xor_sync(0xffffffffu, s, 1);
        if (!(tid & 1)) s_inv[r] = 1.f / s;
    }
    __syncthreads();

    const int prow = tid >> 1;
    const int pk   = (tid & 1) * 8;
    const int kkb  = (tid & 1) * 4;
    const __half* P = Pexp + (size_t)z * S_ * S_ + (size_t)(bm + prow) * S_ + pk;
    float* Aout = attn + (size_t)z * S_ * S_ + (size_t)(bm + prow) * S_ + pk;
    const float inv = s_inv[prow];

    const int vu = wid;
    const int vn = lane * 2;
    const __half* Vbase = Vg + (size_t)zb * S_ * D_ + (size_t)zh * DK_ + vn;

    float acc[2][4][4];
#pragma unroll
    for (int i = 0; i < 2; i++)
#pragma unroll
        for (int j = 0; j < 4; j++)
#pragma unroll
            for (int e = 0; e < 4; e++) acc[i][j][e] = 0.f;

    const int NIT = S_ / 16;

    // stage 0: load, write attn, STS
    {
        uint4 p0 = *(const uint4*)(P);
        __half2 h0 = *(__half2*)&p0.x, h1 = *(__half2*)&p0.y;
        __half2 h2 = *(__half2*)&p0.z, h3 = *(__half2*)&p0.w;
        float4 o0, o1;
        o0.x = __low2float(h0) * inv;  o0.y = __high2float(h0) * inv;
        o0.z = __low2float(h1) * inv;  o0.w = __high2float(h1) * inv;
        o1.x = __low2float(h2) * inv;  o1.y = __high2float(h2) * inv;
        o1.z = __low2float(h3) * inv;  o1.w = __high2float(h3) * inv;
        *(float4*)(Aout)     = o0;
        *(float4*)(Aout + 4) = o1;
        __half2 e0 = *(const __half2*)(Vbase + (size_t)(2 * vu) * D_);
        __half2 e1 = *(const __half2*)(Vbase + (size_t)(2 * vu + 1) * D_);
        STS8HU(Ps[0], kkb, prow, p0);
        __half2 w0 = __lows2half2(e0, e1);
        __half2 w1 = __highs2half2(e0, e1);
        Vs[0][vu][vn]     = *(uint32_t*)&w0;
        Vs[0][vu][vn + 1] = *(uint32_t*)&w1;
    }
    // preload it=1 into regs A
    uint4 phA = {0,0,0,0}, phB;
    __half2 veA, voA, veB, voB;
    phA = *(const uint4*)(P + 16);
    veA = *(const __half2*)(Vbase + (size_t)(16 + 2 * vu) * D_);
    voA = *(const __half2*)(Vbase + (size_t)(16 + 2 * vu + 1) * D_);
    __syncthreads();

    const int mg = wm * 32 + (lane >> 2);
    const int ng = wn * 32 + (lane >> 2);
    const int kl = lane & 3;

#pragma unroll 2
    for (int it = 0; it < NIT; it++) {
        const int cur = it & 1;
        // prefetch it+2 into regs B
        if (it + 2 < NIT) {
            const int k0 = (it + 2) * 16;
            phB = *(const uint4*)(P + k0);
            veB = *(const __half2*)(Vbase + (size_t)(k0 + 2 * vu) * D_);
            voB = *(const __half2*)(Vbase + (size_t)(k0 + 2 * vu + 1) * D_);
        }
        // compute current stage
        {
            uint32_t af[2][4];
#pragma unroll
            for (int i = 0; i < 2; i++) {
                af[i][0] = Ps[cur][kl    ][mg + i * 16];
                af[i][1] = Ps[cur][kl    ][mg + i * 16 + 8];
                af[i][2] = Ps[cur][kl + 4][mg + i * 16];
                af[i][3] = Ps[cur][kl + 4][mg + i * 16 + 8];
            }
            uint32_t bf[4][2];
#pragma unroll
            for (int j = 0; j < 4; j++) {
                bf[j][0] = Vs[cur][kl    ][ng + j * 8];
                bf[j][1] = Vs[cur][kl + 4][ng + j * 8];
            }
#pragma unroll
            for (int j = 0; j < 4; j++)
#pragma unroll
                for (int i = 0; i < 2; i++)
                    mma_f16(acc[i][j], af[i][0], af[i][1], af[i][2], af[i][3],
                            bf[j][0], bf[j][1]);
        }
        if (it + 1 < NIT) {
            const int k1 = (it + 1) * 16;
            // attn write for it+1 from regs A
            __half2 h0 = *(__half2*)&phA.x, h1 = *(__half2*)&phA.y;
            __half2 h2 = *(__half2*)&phA.z, h3 = *(__half2*)&phA.w;
            float4 o0, o1;
            o0.x = __low2float(h0) * inv;  o0.y = __high2float(h0) * inv;
            o0.z = __low2float(h1) * inv;  o0.w = __high2float(h1) * inv;
            o1.x = __low2float(h2) * inv;  o1.y = __high2float(h2) * inv;
            o1.z = __low2float(h3) * inv;  o1.w = __high2float(h3) * inv;
            *(float4*)(Aout + k1)     = o0;
            *(float4*)(Aout + k1 + 4) = o1;
            STS8HU(Ps[cur ^ 1], kkb, prow, phA);
            __half2 w0 = __lows2half2(veA, voA);
            __half2 w1 = __highs2half2(veA, voA);
            Vs[cur ^ 1][vu][vn]     = *(uint32_t*)&w0;
            Vs[cur ^ 1][vu][vn + 1] = *(uint32_t*)&w1;
            __syncthreads();
        }
        phA = phB; veA = veB; voA = voB;
    }

    __half* Cc = ctx + (size_t)zb * S_ * D_ + (size_t)zh * DK_;
    const int row0 = bm + wm * 32 + (lane >> 2);
    const int col0 = wn * 32 + (lane & 3) * 2;
#pragma unroll
    for (int i = 0; i < 2; i++) {
        const float ilo = s_inv[wm * 32 + (lane >> 2) + i * 16];
        const float ihi = s_inv[wm * 32 + (lane >> 2) + i * 16 + 8];
#pragma unroll
        for (int j = 0; j < 4; j++) {
            const int r = row0 + i * 16;
            const int c = col0 + j * 8;
            *(uint32_t*)&Cc[(size_t)r * D_ + c]       = f2h2(acc[i][j][0] * ilo, acc[i][j][1] * ilo);
            *(uint32_t*)&Cc[(size_t)(r + 8) * D_ + c] = f2h2(acc[i][j][2] * ihi, acc[i][j][3] * ihi);
        }
    }
}

// ---------------- launch ----------------
extern "C" void kernel_launch(void* const* d_in, const int* in_sizes, int n_in,
                              void* d_out, int out_size)
{
    const float* query = (const float*)d_in[0];
    const float* key   = (const float*)d_in[1];
    const float* value = (const float*)d_in[2];
    const float* Wq    = (const float*)d_in[3];
    const float* bq    = (const float*)d_in[4];
    const float* Wk    = (const float*)d_in[5];
    const float* bk    = (const float*)d_in[6];
    const float* Wv    = (const float*)d_in[7];
    const float* bv    = (const float*)d_in[8];
    const float* Wo    = (const float*)d_in[9];
    const float* bo    = (const float*)d_in[10];

    float* out  = (float*)d_out;                          // (B,S,D)
    float* attn = out + (size_t)B_ * S_ * D_;             // (B,H,S,S)

    __half *qh, *kh, *vh, *ctxh, *xq, *xk, *xv, *wq, *wk, *wv, *wo, *ph;
    float *part;
    cudaGetSymbolAddress((void**)&qh,   g_qh);
    cudaGetSymbolAddress((void**)&kh,   g_kh);
    cudaGetSymbolAddress((void**)&vh,   g_vh);
    cudaGetSymbolAddress((void**)&ctxh, g_ctxh);
    cudaGetSymbolAddress((void**)&xq,   g_xq);
    cudaGetSymbolAddress((void**)&xk,   g_xk);
    cudaGetSymbolAddress((void**)&xv,   g_xv);
    cudaGetSymbolAddress((void**)&wq,   g_wq);
    cudaGetSymbolAddress((void**)&wk,   g_wk);
    cudaGetSymbolAddress((void**)&wv,   g_wv);
    cudaGetSymbolAddress((void**)&wo,   g_wo);
    cudaGetSymbolAddress((void**)&ph,   g_ph);
    cudaGetSymbolAddress((void**)&part, g_partial);

    // 0) convert inputs + weights to fp16 once
    to_half7<<<8192, 256>>>(query, key, value, Wq, Wk, Wv, Wo,
                            xq, xk, xv, wq, wk, wv, wo);

    // 1) fused q/k/v projections (grid.z = 3)
    dim3 pgrid(D_ / 128, (B_ * S_) / 128, 3);
    proj3_h<__half><<<pgrid, 256>>>(xq, xk, xv, wq, wk, wv, bq, bk, bv, qh, kh, vh);

    // 2) QK^T -> exp fp16 scratch + partials
    dim3 qkgrid(S_ / 128, S_ / 128, B_ * H_);
    qk_h<<<qkgrid, 256>>>(qh, kh, ph, part);

    // 3) normalized attn write + ctx = inv * (expP @ V)
    dim3 pvgrid(S_ / 128, B_ * H_);
    pv_h<<<pvgrid, 256>>>(ph, attn, vh, ctxh, part);

    // 4) output projection (fp16 x fp16 -> fp32)
    dim3 ogrid(D_ / 128, (B_ * S_) / 128, 1);
    proj3_h<float><<<ogrid, 256>>>(ctxh, ctxh, ctxh, wo, wo, wo, bo, bo, bo, out, out, out);
}